// round 6
// baseline (speedup 1.0000x reference)
#include <cuda_runtime.h>
#include <float.h>
#include <stdint.h>

#define NBB 4
#define NNN 4096
#define NKK 40
#define BN_ (NBB*NNN)            // 16384
#define BNK (BN_*NKK)            // 655360
#define EDGE_PPT 2               // points per tile (A = 96 rows)
#define EDGE_ITER 4              // tiles per block -> 8 points per block
#define KNN_Q 4                  // queries per knn block

// ---------------- static scratch ----------------
__device__ float    d_nrm[BN_];
__device__ int      d_idx[BNK];
__device__ float    d_xcat[(size_t)BN_*192];   // [x1|x2|x3] per point
__device__ float    d_PQ[(size_t)BN_*128];     // P (0..63) | Q (64..127)
__device__ float    d_h7[(size_t)BN_*512];
__device__ float    d_h8[(size_t)BN_*256];
__device__ float    d_Wpq[128*64];
__device__ unsigned d_gmax[NBB*1024];
__device__ float    d_Gb[NBB*512];

__device__ __forceinline__ unsigned enc_f(float f){
    unsigned u = __float_as_uint(f);
    return (u & 0x80000000u) ? ~u : (u | 0x80000000u);
}
__device__ __forceinline__ float dec_f(unsigned k){
    unsigned u = (k & 0x80000000u) ? (k & 0x7FFFFFFFu) : ~k;
    return __uint_as_float(u);
}
__device__ __forceinline__ uint32_t f2tf(float f){
    uint32_t r; asm("cvt.rna.tf32.f32 %0, %1;" : "=r"(r) : "f"(f)); return r;
}
__device__ __forceinline__ void mma_tf32(float4 &c, const uint32_t* a, const uint32_t* b){
    asm volatile("mma.sync.aligned.m16n8k8.row.col.f32.tf32.tf32.f32 "
        "{%0,%1,%2,%3}, {%4,%5,%6,%7}, {%8,%9}, {%0,%1,%2,%3};"
        : "+f"(c.x), "+f"(c.y), "+f"(c.z), "+f"(c.w)
        : "r"(a[0]), "r"(a[1]), "r"(a[2]), "r"(a[3]), "r"(b[0]), "r"(b[1]));
}

// ---------------- squared norms ----------------
__global__ void nrm_kernel(const float* __restrict__ x, float* __restrict__ nrm){
    int i = blockIdx.x*256 + threadIdx.x;
    if (i >= BN_) return;
    int b = i >> 12, n = i & (NNN-1);
    const float* xb = x + (size_t)b*3*NNN;
    float a = xb[n], c = xb[NNN+n], d = xb[2*NNN+n];
    nrm[i] = a*a + c*c + d*d;
}

// ---------------- kNN v3: 4 queries/block, radix select, aggregated atomics
// Downstream of idx is always max-over-k, so any order of the top-40 set is valid.
__global__ void __launch_bounds__(256) knn_radix4(const float* __restrict__ x,
                                                  const float* __restrict__ nrm,
                                                  int* __restrict__ idxo){
    extern __shared__ unsigned dyn[];
    unsigned* keys = dyn;                     // [KNN_Q][NNN]
    unsigned* hist = dyn + KNN_Q*NNN;         // [KNN_Q][256]
    __shared__ float qd[KNN_Q][4];            // qx,qy,qz,qn
    __shared__ unsigned wsum[KNN_Q][2];
    __shared__ unsigned sh_prefix[KNN_Q];
    __shared__ int sh_remain[KNN_Q];
    __shared__ int cnt_hi[KNN_Q], cnt_eq[KNN_Q];

    int blk = blockIdx.x;                     // 0..4095
    int b = blk >> 10;
    int n0 = (blk & 1023) * KNN_Q;
    int tid = threadIdx.x;
    int w = tid >> 5, lane = tid & 31;
    const float* xb = x + (size_t)b*3*NNN;
    const float* nb = nrm + b*NNN;

    if (tid < KNN_Q*4){
        int q = tid >> 2, c = tid & 3;
        int n = n0 + q;
        float v;
        if (c == 0) v = xb[n];
        else if (c == 1) v = xb[NNN+n];
        else if (c == 2) v = xb[2*NNN+n];
        else v = nb[n];
        qd[q][c] = v;
    }
    if (tid < KNN_Q){ sh_prefix[tid] = 0; sh_remain[tid] = NKK;
                      cnt_hi[tid] = 0; cnt_eq[tid] = 0; }
    __syncthreads();

    // distance rows for all 4 queries, candidate data loaded once
    for (int i = tid; i < NNN; i += 256){
        float cx = xb[i], cy = xb[NNN+i], cz = xb[2*NNN+i], cn = nb[i];
        #pragma unroll
        for (int q = 0; q < KNN_Q; q++){
            float d = 2.f*(qd[q][0]*cx + qd[q][1]*cy + qd[q][2]*cz) - qd[q][3] - cn;
            keys[q*NNN + i] = enc_f(d);
        }
    }

    // selection: warp pair (w>>1) owns query q; g in 0..63
    int q = w >> 1;
    int g = (w & 1)*32 + lane;
    unsigned* kq = keys + q*NNN;
    unsigned* hq = hist + q*256;

    #pragma unroll
    for (int pass = 0; pass < 4; pass++){
        int shift = 24 - 8*pass;
        // zero all hists
        for (int i = tid; i < KNN_Q*256; i += 256) hist[i] = 0;
        __syncthreads();
        unsigned pfx = sh_prefix[q];
        int remain = sh_remain[q];
        for (int i = g; i < NNN; i += 64){
            unsigned k = kq[i];
            if (pass == 0){
                unsigned bin = k >> 24;
                unsigned mm = __match_any_sync(0xffffffffu, bin);
                if (lane == __ffs(mm)-1) atomicAdd(&hq[bin], __popc(mm));
            } else {
                bool pred = (k >> (shift + 8)) == pfx;
                unsigned msk = __ballot_sync(0xffffffffu, pred);
                if (pred){
                    unsigned bin = (k >> shift) & 255u;
                    unsigned mm = __match_any_sync(msk, bin);
                    if (lane == __ffs(mm)-1) atomicAdd(&hq[bin], __popc(mm));
                }
            }
        }
        __syncthreads();
        // suffix select: thread g owns bins 4g..4g+3
        unsigned v0 = hq[4*g], v1 = hq[4*g+1], v2 = hq[4*g+2], v3 = hq[4*g+3];
        unsigned s = v0+v1+v2+v3;
        unsigned acc = s;
        #pragma unroll
        for (int off = 1; off < 32; off <<= 1){
            unsigned t = __shfl_down_sync(0xffffffffu, acc, off);
            if (lane + off < 32) acc += t;
        }
        if (lane == 0) wsum[q][w & 1] = acc;
        __syncthreads();
        unsigned S_after = acc - s + ((w & 1) == 0 ? wsum[q][1] : 0);
        // bins descending within this thread
        unsigned suf3 = S_after + v3;
        unsigned suf2 = suf3 + v2;
        unsigned suf1 = suf2 + v1;
        unsigned suf0 = suf1 + v0;
        unsigned R = (unsigned)remain;
        unsigned binw = 0xffffffffu, abovew = 0;
        if (suf3 >= R && S_after < R){ binw = 4*g+3; abovew = S_after; }
        else if (suf2 >= R && suf3 < R){ binw = 4*g+2; abovew = suf3; }
        else if (suf1 >= R && suf2 < R){ binw = 4*g+1; abovew = suf2; }
        else if (suf0 >= R && suf1 < R){ binw = 4*g;   abovew = suf1; }
        if (binw != 0xffffffffu){
            sh_prefix[q] = (pfx << 8) | binw;
            sh_remain[q] = remain - (int)abovew;
        }
        __syncthreads();
    }

    unsigned thr = sh_prefix[q];
    int rem = sh_remain[q];
    int* out = idxo + ((size_t)((b<<12) + n0 + q))*NKK;
    for (int i = g; i < NNN; i += 64){
        if (kq[i] > thr){ int pos = atomicAdd(&cnt_hi[q], 1); out[pos] = i; }
    }
    __syncthreads();
    int base = cnt_hi[q];
    for (int i = g; i < NNN; i += 64){
        if (kq[i] == thr){
            int pos = atomicAdd(&cnt_eq[q], 1);
            if (pos < rem) out[base + pos] = i;
        }
    }
}

// ---------------- P/Q from coords (stage 1) --------------------------------
__global__ void pq1_kernel(const float* __restrict__ x, const float* __restrict__ W1,
                           float* __restrict__ PQ){
    int i = blockIdx.x*256 + threadIdx.x;
    int c = i & 63; int p = i >> 6;
    int b = p >> 12, n = p & (NNN-1);
    const float* xb = x + (size_t)b*3*NNN + n;
    float x0 = xb[0], x1 = xb[NNN], x2 = xb[2*NNN];
    const float* w = W1 + c*6;
    float pv = x0*w[0] + x1*w[1] + x2*w[2];
    float qv = x0*(w[3]-w[0]) + x1*(w[4]-w[1]) + x2*(w[5]-w[2]);
    PQ[(size_t)p*128 + c]      = pv;
    PQ[(size_t)p*128 + 64 + c] = qv;
}

// ---------------- weight prep: W (64x128) -> Wpq (128x64) ------------------
__global__ void wprep_kernel(const float* __restrict__ W, float* __restrict__ Wpq){
    int i = blockIdx.x*256 + threadIdx.x;
    int c = i & 63; int r = i >> 6;
    float v;
    if (r < 64) v = W[r*128 + c];
    else { int o = r - 64; v = W[o*128 + 64 + c] - W[o*128 + c]; }
    Wpq[r*64 + c] = v;
}

// ---------------- fused edge conv via tf32 mma, 2 points per tile ----------
__global__ void __launch_bounds__(256) fused_edge_tc(
        const float* __restrict__ PQ,
        const float* __restrict__ sa, const float* __restrict__ ba,
        const float* __restrict__ W2,
        const float* __restrict__ sb, const float* __restrict__ bb,
        const int* __restrict__ idx, float* __restrict__ xout, int ostride)
{
    __shared__ uint32_t As[96][68];
    __shared__ uint32_t Ws[64][68];
    __shared__ float qrow[2*64], sav[64], bav[64];
    __shared__ int js[2*40];
    int tid = threadIdx.x;
    int w = tid >> 5, lane = tid & 31;
    int gid = lane >> 2, tig = lane & 3;
    int pt = w >> 2, wn = w & 3;

    for (int i = tid; i < 4096; i += 256) Ws[i>>6][i&63] = f2tf(W2[i]);
    if (tid < 64){ sav[tid] = sa[tid]; bav[tid] = ba[tid]; }
    for (int i = tid; i < 8*68; i += 256){
        As[40 + i/68][i%68] = 0u;
        As[88 + i/68][i%68] = 0u;
    }

    int c0 = wn*16 + 2*tig;
    float se0 = sb[c0],   oe0 = bb[c0],   se1 = sb[c0+1],   oe1 = bb[c0+1];
    float se2 = sb[c0+8], oe2 = bb[c0+8], se3 = sb[c0+9],   oe3 = bb[c0+9];

    int p0 = blockIdx.x * (EDGE_PPT*EDGE_ITER);
    for (int it = 0; it < EDGE_ITER; it++){
        int pb = p0 + it*EDGE_PPT;
        if (tid < 128) qrow[tid] = PQ[(size_t)(pb + (tid>>6))*128 + 64 + (tid & 63)];
        if (tid < 80)  js[tid] = idx[(size_t)(pb + (tid>=40))*NKK + (tid>=40 ? tid-40 : tid)];
        __syncthreads();
        int base0 = ((pb)   >> 12) << 12;
        int base1 = ((pb+1) >> 12) << 12;
        for (int e = tid; e < 2*640; e += 256){
            int lpt = e / 640;
            int r = e - lpt*640;
            int k = r >> 4, c4 = r & 15;
            int bse = lpt ? base1 : base0;
            float4 v4 = *(const float4*)&PQ[((size_t)(bse + js[lpt*40 + k]))*128 + c4*4];
            float4 q4 = *(const float4*)&qrow[lpt*64 + c4*4];
            float4 sv = *(const float4*)&sav[c4*4];
            float4 bv = *(const float4*)&bav[c4*4];
            float z0 = sv.x*(v4.x+q4.x)+bv.x; z0 = z0>0.f? z0 : 0.2f*z0;
            float z1 = sv.y*(v4.y+q4.y)+bv.y; z1 = z1>0.f? z1 : 0.2f*z1;
            float z2 = sv.z*(v4.z+q4.z)+bv.z; z2 = z2>0.f? z2 : 0.2f*z2;
            float z3 = sv.w*(v4.w+q4.w)+bv.w; z3 = z3>0.f? z3 : 0.2f*z3;
            uint4 u = {f2tf(z0), f2tf(z1), f2tf(z2), f2tf(z3)};
            *(uint4*)&As[lpt*48 + k][c4*4] = u;
        }
        __syncthreads();

        float4 acc[3][2];
        #pragma unroll
        for (int mt=0;mt<3;mt++){ acc[mt][0]=make_float4(0.f,0.f,0.f,0.f);
                                  acc[mt][1]=make_float4(0.f,0.f,0.f,0.f); }
        int rbase = pt*48;
        #pragma unroll
        for (int k0=0;k0<64;k0+=8){
            uint32_t bf[2][2];
            #pragma unroll
            for (int nt=0;nt<2;nt++){
                bf[nt][0] = Ws[wn*16 + nt*8 + gid][k0+tig];
                bf[nt][1] = Ws[wn*16 + nt*8 + gid][k0+tig+4];
            }
            #pragma unroll
            for (int mt=0;mt<3;mt++){
                uint32_t af[4];
                int r = rbase + mt*16;
                af[0] = As[r+gid  ][k0+tig];
                af[1] = As[r+gid+8][k0+tig];
                af[2] = As[r+gid  ][k0+tig+4];
                af[3] = As[r+gid+8][k0+tig+4];
                mma_tf32(acc[mt][0], af, bf[0]);
                mma_tf32(acc[mt][1], af, bf[1]);
            }
        }
        float m00=-FLT_MAX, m01=-FLT_MAX, m10=-FLT_MAX, m11=-FLT_MAX;
        #pragma unroll
        for (int mt=0;mt<3;mt++){
            float z;
            z = se0*acc[mt][0].x + oe0; z = z>0.f? z : 0.2f*z; m00 = fmaxf(m00, z);
            z = se1*acc[mt][0].y + oe1; z = z>0.f? z : 0.2f*z; m01 = fmaxf(m01, z);
            z = se2*acc[mt][1].x + oe2; z = z>0.f? z : 0.2f*z; m10 = fmaxf(m10, z);
            z = se3*acc[mt][1].y + oe3; z = z>0.f? z : 0.2f*z; m11 = fmaxf(m11, z);
            if (mt < 2){
                z = se0*acc[mt][0].z + oe0; z = z>0.f? z : 0.2f*z; m00 = fmaxf(m00, z);
                z = se1*acc[mt][0].w + oe1; z = z>0.f? z : 0.2f*z; m01 = fmaxf(m01, z);
                z = se2*acc[mt][1].z + oe2; z = z>0.f? z : 0.2f*z; m10 = fmaxf(m10, z);
                z = se3*acc[mt][1].w + oe3; z = z>0.f? z : 0.2f*z; m11 = fmaxf(m11, z);
            }
        }
        #pragma unroll
        for (int off=4; off<32; off<<=1){
            m00 = fmaxf(m00, __shfl_xor_sync(0xffffffffu, m00, off));
            m01 = fmaxf(m01, __shfl_xor_sync(0xffffffffu, m01, off));
            m10 = fmaxf(m10, __shfl_xor_sync(0xffffffffu, m10, off));
            m11 = fmaxf(m11, __shfl_xor_sync(0xffffffffu, m11, off));
        }
        if (gid == 0){
            int p = pb + pt;
            xout[(size_t)p*ostride + c0]     = m00;
            xout[(size_t)p*ostride + c0+1]   = m01;
            xout[(size_t)p*ostride + c0+8]   = m10;
            xout[(size_t)p*ostride + c0+9]   = m11;
        }
        __syncthreads();
    }
}

// ---------------- stage 3: gather + BN/lrelu + max_k -----------------------
__global__ void maxgather_kernel(const float* __restrict__ PQ,
                                 const float* __restrict__ s, const float* __restrict__ bias,
                                 const int* __restrict__ idx,
                                 float* __restrict__ xout, int ostride){
    int i = blockIdx.x*256 + threadIdx.x;
    int o = i & 63, p = i >> 6; int b = p >> 12;
    float qv = PQ[(size_t)p*128 + 64 + o];
    float sc = s[o], bv = bias[o];
    const int* ip = idx + (size_t)p*NKK;
    size_t base = (size_t)(b << 12)*128;
    float m = -FLT_MAX;
    #pragma unroll 8
    for (int k=0;k<NKK;k++){
        float v = PQ[base + (size_t)ip[k]*128 + o] + qv;
        v = sc*v + bv;
        v = v>0.f? v : 0.2f*v;
        m = fmaxf(m, v);
    }
    xout[(size_t)p*ostride + o] = m;
}

__global__ void init_gmax(unsigned* g){
    int i = blockIdx.x*256 + threadIdx.x;
    if (i < NBB*1024) g[i] = 0u;
}

// ---------------- Gb[b][o] = sum_c g[b,c] * W7[o,c]  (c < 1024) ------------
__global__ void gb_kernel(const unsigned* __restrict__ gmax, const float* __restrict__ W7,
                          float* __restrict__ Gb){
    int i = blockIdx.x*256 + threadIdx.x;
    int o = i & 511; int b = i >> 9;
    const unsigned* gm = gmax + b*1024;
    const float* w = W7 + (size_t)o*1216;
    float a0=0.f,a1=0.f,a2=0.f,a3=0.f;
    for (int c=0;c<1024;c+=4){
        a0 += dec_f(gm[c+0])*w[c+0];
        a1 += dec_f(gm[c+1])*w[c+1];
        a2 += dec_f(gm[c+2])*w[c+2];
        a3 += dec_f(gm[c+3])*w[c+3];
    }
    Gb[(size_t)b*512 + o] = (a0+a1)+(a2+a3);
}

// ---------------- tf32 tensor-core GEMM, 128x128 tile, double-buffered -----
__global__ void __launch_bounds__(256,2) gemm_tc(
        const float* __restrict__ A, int lda,
        const float* __restrict__ W, int ldw,
        const float* __restrict__ s, const float* __restrict__ bias,
        const float* __restrict__ Gb,
        float* __restrict__ C, int ldc, unsigned* gmax,
        int Kd, int Nd, float leak, int mode)
{
    __shared__ uint32_t As[2][128][20];
    __shared__ uint32_t Ws[2][128][20];
    int m0 = blockIdx.x*128, n0 = blockIdx.y*128;
    int tid = threadIdx.x, lane = tid & 31, w = tid >> 5;
    int gid = lane >> 2, tig = lane & 3;
    int wm = (w >> 2)*64, wn = (w & 3)*32;
    float4 acc[4][4];
    #pragma unroll
    for (int mt=0;mt<4;mt++)
        #pragma unroll
        for (int nt=0;nt<4;nt++) acc[mt][nt] = make_float4(0.f,0.f,0.f,0.f);

    int lr = tid >> 1, lq = (tid & 1)*8;
    const float* Ap = A + (size_t)(m0+lr)*lda + lq;
    const float* Wp = W + (size_t)(n0+lr)*ldw + lq;

    int nk = Kd >> 4;
    float4 ta0 = *(const float4*)(Ap);
    float4 ta1 = *(const float4*)(Ap + 4);
    float4 tw0 = *(const float4*)(Wp);
    float4 tw1 = *(const float4*)(Wp + 4);
    {
        uint4 ua0 = {f2tf(ta0.x),f2tf(ta0.y),f2tf(ta0.z),f2tf(ta0.w)};
        uint4 ua1 = {f2tf(ta1.x),f2tf(ta1.y),f2tf(ta1.z),f2tf(ta1.w)};
        uint4 uw0 = {f2tf(tw0.x),f2tf(tw0.y),f2tf(tw0.z),f2tf(tw0.w)};
        uint4 uw1 = {f2tf(tw1.x),f2tf(tw1.y),f2tf(tw1.z),f2tf(tw1.w)};
        *(uint4*)&As[0][lr][lq]   = ua0;
        *(uint4*)&As[0][lr][lq+4] = ua1;
        *(uint4*)&Ws[0][lr][lq]   = uw0;
        *(uint4*)&Ws[0][lr][lq+4] = uw1;
    }
    __syncthreads();

    for (int c = 0; c < nk; c++){
        int cur = c & 1;
        if (c + 1 < nk){
            int k0 = (c+1) << 4;
            ta0 = *(const float4*)(Ap + k0);
            ta1 = *(const float4*)(Ap + k0 + 4);
            tw0 = *(const float4*)(Wp + k0);
            tw1 = *(const float4*)(Wp + k0 + 4);
        }
        #pragma unroll
        for (int ks=0; ks<16; ks+=8){
            uint32_t bf[4][2];
            #pragma unroll
            for (int nt=0;nt<4;nt++){
                int n = wn + nt*8 + gid;
                bf[nt][0] = Ws[cur][n][ks+tig];
                bf[nt][1] = Ws[cur][n][ks+tig+4];
            }
            #pragma unroll
            for (int mt=0;mt<4;mt++){
                uint32_t af[4];
                int r = wm + mt*16;
                af[0] = As[cur][r+gid  ][ks+tig];
                af[1] = As[cur][r+gid+8][ks+tig];
                af[2] = As[cur][r+gid  ][ks+tig+4];
                af[3] = As[cur][r+gid+8][ks+tig+4];
                #pragma unroll
                for (int nt=0;nt<4;nt++) mma_tf32(acc[mt][nt], af, bf[nt]);
            }
        }
        if (c + 1 < nk){
            int nxt = cur ^ 1;
            uint4 ua0 = {f2tf(ta0.x),f2tf(ta0.y),f2tf(ta0.z),f2tf(ta0.w)};
            uint4 ua1 = {f2tf(ta1.x),f2tf(ta1.y),f2tf(ta1.z),f2tf(ta1.w)};
            uint4 uw0 = {f2tf(tw0.x),f2tf(tw0.y),f2tf(tw0.z),f2tf(tw0.w)};
            uint4 uw1 = {f2tf(tw1.x),f2tf(tw1.y),f2tf(tw1.z),f2tf(tw1.w)};
            *(uint4*)&As[nxt][lr][lq]   = ua0;
            *(uint4*)&As[nxt][lr][lq+4] = ua1;
            *(uint4*)&Ws[nxt][lr][lq]   = uw0;
            *(uint4*)&Ws[nxt][lr][lq+4] = uw1;
            __syncthreads();
        }
    }

    int b = m0 >> 12;
    if (mode == 0){
        #pragma unroll
        for (int mt=0;mt<4;mt++){
            int r0 = m0 + wm + mt*16 + gid;
            #pragma unroll
            for (int nt=0;nt<4;nt++){
                int cg = n0 + wn + nt*8 + 2*tig;
                float gx = 0.f, gy = 0.f;
                if (Gb){ gx = Gb[(size_t)b*Nd + cg]; gy = Gb[(size_t)b*Nd + cg + 1]; }
                float sx=1.f, sy=1.f, bx=0.f, by=0.f;
                if (s){ sx=s[cg]; sy=s[cg+1]; bx=bias[cg]; by=bias[cg+1]; }
                else if (bias){ bx=bias[cg]; by=bias[cg+1]; }
                float4 a = acc[mt][nt];
                float z0 = sx*(a.x+gx)+bx; z0 = z0>0.f? z0 : leak*z0;
                float z1 = sy*(a.y+gy)+by; z1 = z1>0.f? z1 : leak*z1;
                float z2 = sx*(a.z+gx)+bx; z2 = z2>0.f? z2 : leak*z2;
                float z3 = sy*(a.w+gy)+by; z3 = z3>0.f? z3 : leak*z3;
                *(float2*)&C[(size_t)r0*ldc + cg]     = make_float2(z0,z1);
                *(float2*)&C[(size_t)(r0+8)*ldc + cg] = make_float2(z2,z3);
            }
        }
    } else {
        #pragma unroll
        for (int nt=0;nt<4;nt++){
            int cg = n0 + wn + nt*8 + 2*tig;
            float sx=s[cg], bx=bias[cg], sy=s[cg+1], by=bias[cg+1];
            float mx=-FLT_MAX, my=-FLT_MAX;
            #pragma unroll
            for (int mt=0;mt<4;mt++){
                float4 a = acc[mt][nt];
                float z;
                z = sx*a.x+bx; z = z>0.f? z : leak*z; mx = fmaxf(mx,z);
                z = sx*a.z+bx; z = z>0.f? z : leak*z; mx = fmaxf(mx,z);
                z = sy*a.y+by; z = z>0.f? z : leak*z; my = fmaxf(my,z);
                z = sy*a.w+by; z = z>0.f? z : leak*z; my = fmaxf(my,z);
            }
            #pragma unroll
            for (int off=4; off<32; off<<=1){
                mx = fmaxf(mx, __shfl_xor_sync(0xffffffffu, mx, off));
                my = fmaxf(my, __shfl_xor_sync(0xffffffffu, my, off));
            }
            if (gid == 0){
                atomicMax(&gmax[b*1024 + cg],     enc_f(mx));
                atomicMax(&gmax[b*1024 + cg + 1], enc_f(my));
            }
        }
    }
}

// ---------------- small fp32 GEMM kept for conv9 (transposed store) --------
__global__ void __launch_bounds__(256,2) gemm128(
        const float* __restrict__ A, int lda,
        const float* __restrict__ W, int ldw,
        const float* __restrict__ bias,
        float* __restrict__ C, int Kd, int Nd)
{
    __shared__ float As[8][132];
    __shared__ float Ws[8][132];
    int m0 = blockIdx.x*128, n0 = blockIdx.y*128;
    int tid = threadIdx.x;
    int hr = tid >> 1;
    int kq = (tid & 1)*4;
    const float* Ap = A + (size_t)(m0 + hr)*lda + kq;
    bool wval = (n0 + hr) < Nd;
    const float* Wp = W + (size_t)(n0 + (wval ? hr : 0))*ldw + kq;
    int tx = tid & 15, ty = tid >> 4;
    float acc[8][8];
    #pragma unroll
    for (int i=0;i<8;i++)
        #pragma unroll
        for (int j=0;j<8;j++) acc[i][j]=0.f;

    for (int k0 = 0; k0 < Kd; k0 += 8){
        float4 a4 = *(const float4*)(Ap + k0);
        float4 w4 = wval ? *(const float4*)(Wp + k0) : make_float4(0.f,0.f,0.f,0.f);
        As[kq+0][hr]=a4.x; As[kq+1][hr]=a4.y; As[kq+2][hr]=a4.z; As[kq+3][hr]=a4.w;
        Ws[kq+0][hr]=w4.x; Ws[kq+1][hr]=w4.y; Ws[kq+2][hr]=w4.z; Ws[kq+3][hr]=w4.w;
        __syncthreads();
        #pragma unroll
        for (int k=0;k<8;k++){
            float4 a0 = *(const float4*)&As[k][ty*4];
            float4 a1 = *(const float4*)&As[k][64+ty*4];
            float4 w0 = *(const float4*)&Ws[k][tx*4];
            float4 w1 = *(const float4*)&Ws[k][64+tx*4];
            float ar[8] = {a0.x,a0.y,a0.z,a0.w,a1.x,a1.y,a1.z,a1.w};
            float wr[8] = {w0.x,w0.y,w0.z,w0.w,w1.x,w1.y,w1.z,w1.w};
            #pragma unroll
            for (int i=0;i<8;i++)
                #pragma unroll
                for (int j=0;j<8;j++) acc[i][j] += ar[i]*wr[j];
        }
        __syncthreads();
    }
    #pragma unroll
    for (int i=0;i<8;i++){
        int m = m0 + (i<4 ? ty*4+i : 64 + ty*4 + (i-4));
        int bb_ = m >> 12, nn = m & (NNN-1);
        #pragma unroll
        for (int j=0;j<8;j++){
            int n = n0 + (j<4 ? tx*4+j : 64 + tx*4 + (j-4));
            if (n < Nd){
                float z = acc[i][j] + (bias ? bias[n] : 0.f);
                C[((size_t)bb_*Nd + n)*NNN + nn] = z;
            }
        }
    }
}

// ---------------------------------------------------------------------------
extern "C" void kernel_launch(void* const* d_in, const int* in_sizes, int n_in,
                              void* d_out, int out_size){
    const float* x  = (const float*)d_in[0];
    const float* W1 = (const float*)d_in[1];
    const float* s1 = (const float*)d_in[2];
    const float* b1 = (const float*)d_in[3];
    const float* W2 = (const float*)d_in[4];
    const float* s2 = (const float*)d_in[5];
    const float* b2 = (const float*)d_in[6];
    const float* W3 = (const float*)d_in[7];
    const float* s3 = (const float*)d_in[8];
    const float* b3 = (const float*)d_in[9];
    const float* W4 = (const float*)d_in[10];
    const float* s4 = (const float*)d_in[11];
    const float* b4 = (const float*)d_in[12];
    const float* W5 = (const float*)d_in[13];
    const float* s5 = (const float*)d_in[14];
    const float* b5 = (const float*)d_in[15];
    const float* W6 = (const float*)d_in[16];
    const float* s6 = (const float*)d_in[17];
    const float* b6 = (const float*)d_in[18];
    const float* W7 = (const float*)d_in[19];
    const float* s7 = (const float*)d_in[20];
    const float* b7 = (const float*)d_in[21];
    const float* W8 = (const float*)d_in[22];
    const float* s8 = (const float*)d_in[23];
    const float* b8 = (const float*)d_in[24];
    const float* W9 = (const float*)d_in[25];
    const float* b9 = (const float*)d_in[26];
    float* out = (float*)d_out;

    float *nrm,*xcat,*PQ,*h7,*h8,*Wpq,*Gb; int* idx; unsigned* gmax;
    cudaGetSymbolAddress((void**)&nrm,  d_nrm);
    cudaGetSymbolAddress((void**)&idx,  d_idx);
    cudaGetSymbolAddress((void**)&xcat, d_xcat);
    cudaGetSymbolAddress((void**)&PQ,   d_PQ);
    cudaGetSymbolAddress((void**)&h7,   d_h7);
    cudaGetSymbolAddress((void**)&h8,   d_h8);
    cudaGetSymbolAddress((void**)&Wpq,  d_Wpq);
    cudaGetSymbolAddress((void**)&gmax, d_gmax);
    cudaGetSymbolAddress((void**)&Gb,   d_Gb);

    const float LK = 0.2f;
    const int edge_blocks = BN_/(EDGE_PPT*EDGE_ITER);
    const int knn_smem = (KNN_Q*NNN + KNN_Q*256)*sizeof(unsigned);   // ~68KB

    static int knn_attr_done = 0;
    if (!knn_attr_done){
        cudaFuncSetAttribute(knn_radix4, cudaFuncAttributeMaxDynamicSharedMemorySize,
                             knn_smem);
        knn_attr_done = 1;
    }

    nrm_kernel<<<64,256>>>(x, nrm);
    knn_radix4<<<BN_/KNN_Q, 256, knn_smem>>>(x, nrm, idx);

    // stage 1: P/Q from coords, fused edge conv (conv1+conv2) + max_k -> x1
    pq1_kernel<<<4096,256>>>(x, W1, PQ);
    fused_edge_tc<<<edge_blocks,256>>>(PQ, s1, b1, W2, s2, b2, idx, xcat + 0, 192);

    // stage 2: P/Q = x1 * Wpq3, fused edge conv (conv3+conv4) + max_k -> x2
    wprep_kernel<<<32,256>>>(W3, Wpq);
    gemm_tc<<<dim3(128,1),256>>>(xcat, 192, Wpq, 64, nullptr, nullptr, nullptr,
                                 PQ, 128, nullptr, 64, 128, 1.f, 0);
    fused_edge_tc<<<edge_blocks,256>>>(PQ, s3, b3, W4, s4, b4, idx, xcat + 64, 192);

    // stage 3: P/Q = x2 * Wpq5, gather + lrelu + max_k -> x3
    wprep_kernel<<<32,256>>>(W5, Wpq);
    gemm_tc<<<dim3(128,1),256>>>(xcat + 64, 192, Wpq, 64, nullptr, nullptr, nullptr,
                                 PQ, 128, nullptr, 64, 128, 1.f, 0);
    maxgather_kernel<<<4096,256>>>(PQ, s5, b5, idx, xcat + 128, 192);

    // conv6 (192 -> 1024) with fused max over N (atomic)
    init_gmax<<<16,256>>>(gmax);
    gemm_tc<<<dim3(128,8),256>>>(xcat, 192, W6, 192, s6, b6, nullptr,
                                 nullptr, 0, gmax, 192, 1024, LK, 2);

    // per-batch bias from g through W7's first 1024 input channels
    gb_kernel<<<8,256>>>(gmax, W7, Gb);

    // conv7: xcat (192) through W7[:,1024:] + Gb  -> h7 (512)
    gemm_tc<<<dim3(128,4),256>>>(xcat, 192, W7 + 1024, 1216, s7, b7, Gb,
                                 h7, 512, nullptr, 192, 512, LK, 0);
    // conv8: 512 -> 256
    gemm_tc<<<dim3(128,2),256>>>(h7, 512, W8, 512, s8, b8, nullptr,
                                 h8, 256, nullptr, 512, 256, LK, 0);
    // conv9: 256 -> 63, + bias, transposed store
    gemm128<<<dim3(128,1),256>>>(h8, 256, W9, 256, b9, out, 256, 63);
}

// round 9
// speedup vs baseline: 1.0756x; 1.0756x over previous
#include <cuda_runtime.h>
#include <float.h>
#include <stdint.h>

#define NBB 4
#define NNN 4096
#define NKK 40
#define BN_ (NBB*NNN)            // 16384
#define BNK (BN_*NKK)            // 655360
#define EDGE_PPT 2               // points per tile (A = 96 rows)
#define EDGE_ITER 4              // tiles per block -> 8 points per block
#define KNN_Q 2                  // queries per knn block (sequential selection)
#define KQ_STRIDE 4100           // padded key row stride (words)

// ---------------- static scratch ----------------
__device__ float    d_nrm[BN_];
__device__ int      d_idx[BNK];
__device__ float    d_xcat[(size_t)BN_*192];   // [x1|x2|x3] per point
__device__ float    d_PQ[(size_t)BN_*128];     // P (0..63) | Q (64..127)
__device__ float    d_h7[(size_t)BN_*512];
__device__ float    d_h8[(size_t)BN_*256];
__device__ float    d_Wpq[128*64];
__device__ unsigned d_gmax[NBB*1024];
__device__ float    d_Gb[NBB*512];

__device__ __forceinline__ unsigned enc_f(float f){
    unsigned u = __float_as_uint(f);
    return (u & 0x80000000u) ? ~u : (u | 0x80000000u);
}
__device__ __forceinline__ float dec_f(unsigned k){
    unsigned u = (k & 0x80000000u) ? (k & 0x7FFFFFFFu) : ~k;
    return __uint_as_float(u);
}
__device__ __forceinline__ uint32_t f2tf(float f){
    uint32_t r; asm("cvt.rna.tf32.f32 %0, %1;" : "=r"(r) : "f"(f)); return r;
}
__device__ __forceinline__ void mma_tf32(float4 &c, const uint32_t* a, const uint32_t* b){
    asm volatile("mma.sync.aligned.m16n8k8.row.col.f32.tf32.tf32.f32 "
        "{%0,%1,%2,%3}, {%4,%5,%6,%7}, {%8,%9}, {%0,%1,%2,%3};"
        : "+f"(c.x), "+f"(c.y), "+f"(c.z), "+f"(c.w)
        : "r"(a[0]), "r"(a[1]), "r"(a[2]), "r"(a[3]), "r"(b[0]), "r"(b[1]));
}

// ---------------- squared norms ----------------
__global__ void nrm_kernel(const float* __restrict__ x, float* __restrict__ nrm){
    int i = blockIdx.x*256 + threadIdx.x;
    if (i >= BN_) return;
    int b = i >> 12, n = i & (NNN-1);
    const float* xb = x + (size_t)b*3*NNN;
    float a = xb[n], c = xb[NNN+n], d = xb[2*NNN+n];
    nrm[i] = a*a + c*c + d*d;
}

// ---------------- kNN: 2 queries/block, shared distance phase, sequential
// full-width radix select per query (order-free top-40 is valid: every
// consumer of idx is a max over k).
__global__ void __launch_bounds__(256) knn_radix2(const float* __restrict__ x,
                                                  const float* __restrict__ nrm,
                                                  int* __restrict__ idxo){
    extern __shared__ unsigned keys[];        // [KNN_Q][KQ_STRIDE]
    __shared__ unsigned hist[256];
    __shared__ unsigned wtot[8];
    __shared__ float qd[KNN_Q][4];
    __shared__ unsigned sh_prefix;
    __shared__ int sh_remain;
    __shared__ int cnt_hi, cnt_eq;

    int blk = blockIdx.x;                     // 0..8191
    int b = blk >> 11;
    int n0 = (blk & 2047) * KNN_Q;
    int tid = threadIdx.x;
    int w = tid >> 5, lane = tid & 31;
    const float* xb = x + (size_t)b*3*NNN;
    const float* nb = nrm + b*NNN;

    if (tid < KNN_Q*4){
        int q = tid >> 2, c = tid & 3;
        int n = n0 + q;
        float v;
        if (c == 0) v = xb[n];
        else if (c == 1) v = xb[NNN+n];
        else if (c == 2) v = xb[2*NNN+n];
        else v = nb[n];
        qd[q][c] = v;
    }
    __syncthreads();

    // distance rows for both queries; candidate data loaded once
    for (int i = tid; i < NNN; i += 256){
        float cx = xb[i], cy = xb[NNN+i], cz = xb[2*NNN+i], cn = nb[i];
        #pragma unroll
        for (int q = 0; q < KNN_Q; q++){
            float d = 2.f*(qd[q][0]*cx + qd[q][1]*cy + qd[q][2]*cz) - qd[q][3] - cn;
            keys[q*KQ_STRIDE + i] = enc_f(d);
        }
    }

    for (int q = 0; q < KNN_Q; q++){
        unsigned* kq = keys + q*KQ_STRIDE;
        if (tid == 0){ sh_prefix = 0; sh_remain = NKK; cnt_hi = 0; cnt_eq = 0; }
        __syncthreads();

        #pragma unroll
        for (int pass = 0; pass < 4; pass++){
            int shift = 24 - 8*pass;
            hist[tid] = 0;
            __syncthreads();
            unsigned pfx = sh_prefix;
            int remain = sh_remain;
            for (int i = tid; i < NNN; i += 256){
                unsigned k = kq[i];
                if (pass == 0){
                    unsigned bin = k >> 24;
                    unsigned mm = __match_any_sync(0xffffffffu, bin);
                    if (lane == __ffs(mm)-1) atomicAdd(&hist[bin], __popc(mm));
                } else {
                    bool pred = (k >> (shift + 8)) == pfx;
                    unsigned msk = __ballot_sync(0xffffffffu, pred);
                    if (pred){
                        unsigned bin = (k >> shift) & 255u;
                        unsigned mm = __match_any_sync(msk, bin);
                        if (lane == __ffs(mm)-1) atomicAdd(&hist[bin], __popc(mm));
                    }
                }
            }
            __syncthreads();
            unsigned v = hist[tid];
            unsigned vv = v;
            #pragma unroll
            for (int off = 1; off < 32; off <<= 1){
                unsigned t = __shfl_down_sync(0xffffffffu, vv, off);
                if (lane + off < 32) vv += t;
            }
            if (lane == 0) wtot[w] = vv;
            __syncthreads();
            unsigned add = 0;
            for (int ww = w + 1; ww < 8; ww++) add += wtot[ww];
            unsigned suftid = vv + add;        // count of keys with bin >= tid
            unsigned above  = suftid - v;      // count with bin > tid
            if (suftid >= (unsigned)remain && above < (unsigned)remain){
                sh_prefix = (pfx << 8) | (unsigned)tid;
                sh_remain = remain - (int)above;
            }
            __syncthreads();
        }
        unsigned thr = sh_prefix;
        int rem = sh_remain;
        int* out = idxo + ((size_t)((b<<12) + n0 + q))*NKK;
        for (int i = tid; i < NNN; i += 256){
            if (kq[i] > thr){ int pos = atomicAdd(&cnt_hi, 1); out[pos] = i; }
        }
        __syncthreads();
        int base = cnt_hi;
        for (int i = tid; i < NNN; i += 256){
            if (kq[i] == thr){
                int pos = atomicAdd(&cnt_eq, 1);
                if (pos < rem) out[base + pos] = i;
            }
        }
        __syncthreads();
    }
}

// ---------------- P/Q from coords (stage 1) --------------------------------
__global__ void pq1_kernel(const float* __restrict__ x, const float* __restrict__ W1,
                           float* __restrict__ PQ){
    int i = blockIdx.x*256 + threadIdx.x;
    int c = i & 63; int p = i >> 6;
    int b = p >> 12, n = p & (NNN-1);
    const float* xb = x + (size_t)b*3*NNN + n;
    float x0 = xb[0], x1 = xb[NNN], x2 = xb[2*NNN];
    const float* w = W1 + c*6;
    float pv = x0*w[0] + x1*w[1] + x2*w[2];
    float qv = x0*(w[3]-w[0]) + x1*(w[4]-w[1]) + x2*(w[5]-w[2]);
    PQ[(size_t)p*128 + c]      = pv;
    PQ[(size_t)p*128 + 64 + c] = qv;
}

// ---------------- weight prep: W (64x128) -> Wpq (128x64) ------------------
__global__ void wprep_kernel(const float* __restrict__ W, float* __restrict__ Wpq){
    int i = blockIdx.x*256 + threadIdx.x;
    int c = i & 63; int r = i >> 6;
    float v;
    if (r < 64) v = W[r*128 + c];
    else { int o = r - 64; v = W[o*128 + 64 + c] - W[o*128 + c]; }
    Wpq[r*64 + c] = v;
}

// ---------------- fused edge conv via tf32 mma, 2 points per tile ----------
__global__ void __launch_bounds__(256) fused_edge_tc(
        const float* __restrict__ PQ,
        const float* __restrict__ sa, const float* __restrict__ ba,
        const float* __restrict__ W2,
        const float* __restrict__ sb, const float* __restrict__ bb,
        const int* __restrict__ idx, float* __restrict__ xout, int ostride)
{
    __shared__ uint32_t As[96][68];
    __shared__ uint32_t Ws[64][68];
    __shared__ float qrow[2*64], sav[64], bav[64];
    __shared__ int js[2*40];
    int tid = threadIdx.x;
    int w = tid >> 5, lane = tid & 31;
    int gid = lane >> 2, tig = lane & 3;
    int pt = w >> 2, wn = w & 3;

    for (int i = tid; i < 4096; i += 256) Ws[i>>6][i&63] = f2tf(W2[i]);
    if (tid < 64){ sav[tid] = sa[tid]; bav[tid] = ba[tid]; }
    for (int i = tid; i < 8*68; i += 256){
        As[40 + i/68][i%68] = 0u;
        As[88 + i/68][i%68] = 0u;
    }

    int c0 = wn*16 + 2*tig;
    float se0 = sb[c0],   oe0 = bb[c0],   se1 = sb[c0+1],   oe1 = bb[c0+1];
    float se2 = sb[c0+8], oe2 = bb[c0+8], se3 = sb[c0+9],   oe3 = bb[c0+9];

    int p0 = blockIdx.x * (EDGE_PPT*EDGE_ITER);
    for (int it = 0; it < EDGE_ITER; it++){
        int pb = p0 + it*EDGE_PPT;
        if (tid < 128) qrow[tid] = PQ[(size_t)(pb + (tid>>6))*128 + 64 + (tid & 63)];
        if (tid < 80)  js[tid] = idx[(size_t)(pb + (tid>=40))*NKK + (tid>=40 ? tid-40 : tid)];
        __syncthreads();
        int base0 = ((pb)   >> 12) << 12;
        int base1 = ((pb+1) >> 12) << 12;
        for (int e = tid; e < 2*640; e += 256){
            int lpt = e / 640;
            int r = e - lpt*640;
            int k = r >> 4, c4 = r & 15;
            int bse = lpt ? base1 : base0;
            float4 v4 = *(const float4*)&PQ[((size_t)(bse + js[lpt*40 + k]))*128 + c4*4];
            float4 q4 = *(const float4*)&qrow[lpt*64 + c4*4];
            float4 sv = *(const float4*)&sav[c4*4];
            float4 bv = *(const float4*)&bav[c4*4];
            float z0 = sv.x*(v4.x+q4.x)+bv.x; z0 = z0>0.f? z0 : 0.2f*z0;
            float z1 = sv.y*(v4.y+q4.y)+bv.y; z1 = z1>0.f? z1 : 0.2f*z1;
            float z2 = sv.z*(v4.z+q4.z)+bv.z; z2 = z2>0.f? z2 : 0.2f*z2;
            float z3 = sv.w*(v4.w+q4.w)+bv.w; z3 = z3>0.f? z3 : 0.2f*z3;
            uint4 u = {f2tf(z0), f2tf(z1), f2tf(z2), f2tf(z3)};
            *(uint4*)&As[lpt*48 + k][c4*4] = u;
        }
        __syncthreads();

        float4 acc[3][2];
        #pragma unroll
        for (int mt=0;mt<3;mt++){ acc[mt][0]=make_float4(0.f,0.f,0.f,0.f);
                                  acc[mt][1]=make_float4(0.f,0.f,0.f,0.f); }
        int rbase = pt*48;
        #pragma unroll
        for (int k0=0;k0<64;k0+=8){
            uint32_t bf[2][2];
            #pragma unroll
            for (int nt=0;nt<2;nt++){
                bf[nt][0] = Ws[wn*16 + nt*8 + gid][k0+tig];
                bf[nt][1] = Ws[wn*16 + nt*8 + gid][k0+tig+4];
            }
            #pragma unroll
            for (int mt=0;mt<3;mt++){
                uint32_t af[4];
                int r = rbase + mt*16;
                af[0] = As[r+gid  ][k0+tig];
                af[1] = As[r+gid+8][k0+tig];
                af[2] = As[r+gid  ][k0+tig+4];
                af[3] = As[r+gid+8][k0+tig+4];
                mma_tf32(acc[mt][0], af, bf[0]);
                mma_tf32(acc[mt][1], af, bf[1]);
            }
        }
        float m00=-FLT_MAX, m01=-FLT_MAX, m10=-FLT_MAX, m11=-FLT_MAX;
        #pragma unroll
        for (int mt=0;mt<3;mt++){
            float z;
            z = se0*acc[mt][0].x + oe0; z = z>0.f? z : 0.2f*z; m00 = fmaxf(m00, z);
            z = se1*acc[mt][0].y + oe1; z = z>0.f? z : 0.2f*z; m01 = fmaxf(m01, z);
            z = se2*acc[mt][1].x + oe2; z = z>0.f? z : 0.2f*z; m10 = fmaxf(m10, z);
            z = se3*acc[mt][1].y + oe3; z = z>0.f? z : 0.2f*z; m11 = fmaxf(m11, z);
            if (mt < 2){
                z = se0*acc[mt][0].z + oe0; z = z>0.f? z : 0.2f*z; m00 = fmaxf(m00, z);
                z = se1*acc[mt][0].w + oe1; z = z>0.f? z : 0.2f*z; m01 = fmaxf(m01, z);
                z = se2*acc[mt][1].z + oe2; z = z>0.f? z : 0.2f*z; m10 = fmaxf(m10, z);
                z = se3*acc[mt][1].w + oe3; z = z>0.f? z : 0.2f*z; m11 = fmaxf(m11, z);
            }
        }
        #pragma unroll
        for (int off=4; off<32; off<<=1){
            m00 = fmaxf(m00, __shfl_xor_sync(0xffffffffu, m00, off));
            m01 = fmaxf(m01, __shfl_xor_sync(0xffffffffu, m01, off));
            m10 = fmaxf(m10, __shfl_xor_sync(0xffffffffu, m10, off));
            m11 = fmaxf(m11, __shfl_xor_sync(0xffffffffu, m11, off));
        }
        if (gid == 0){
            int p = pb + pt;
            xout[(size_t)p*ostride + c0]     = m00;
            xout[(size_t)p*ostride + c0+1]   = m01;
            xout[(size_t)p*ostride + c0+8]   = m10;
            xout[(size_t)p*ostride + c0+9]   = m11;
        }
        __syncthreads();
    }
}

// ---------------- stage 3: gather + BN/lrelu + max_k -----------------------
__global__ void maxgather_kernel(const float* __restrict__ PQ,
                                 const float* __restrict__ s, const float* __restrict__ bias,
                                 const int* __restrict__ idx,
                                 float* __restrict__ xout, int ostride){
    int i = blockIdx.x*256 + threadIdx.x;
    int o = i & 63, p = i >> 6; int b = p >> 12;
    float qv = PQ[(size_t)p*128 + 64 + o];
    float sc = s[o], bv = bias[o];
    const int* ip = idx + (size_t)p*NKK;
    size_t base = (size_t)(b << 12)*128;
    float m = -FLT_MAX;
    #pragma unroll 8
    for (int k=0;k<NKK;k++){
        float v = PQ[base + (size_t)ip[k]*128 + o] + qv;
        v = sc*v + bv;
        v = v>0.f? v : 0.2f*v;
        m = fmaxf(m, v);
    }
    xout[(size_t)p*ostride + o] = m;
}

__global__ void init_gmax(unsigned* g){
    int i = blockIdx.x*256 + threadIdx.x;
    if (i < NBB*1024) g[i] = 0u;
}

// ---------------- Gb[b][o] = sum_c g[b,c] * W7[o,c]  (c < 1024) ------------
__global__ void gb_kernel(const unsigned* __restrict__ gmax, const float* __restrict__ W7,
                          float* __restrict__ Gb){
    int i = blockIdx.x*256 + threadIdx.x;
    int o = i & 511; int b = i >> 9;
    const unsigned* gm = gmax + b*1024;
    const float* w = W7 + (size_t)o*1216;
    float a0=0.f,a1=0.f,a2=0.f,a3=0.f;
    for (int c=0;c<1024;c+=4){
        a0 += dec_f(gm[c+0])*w[c+0];
        a1 += dec_f(gm[c+1])*w[c+1];
        a2 += dec_f(gm[c+2])*w[c+2];
        a3 += dec_f(gm[c+3])*w[c+3];
    }
    Gb[(size_t)b*512 + o] = (a0+a1)+(a2+a3);
}

// ---------------- tf32 tensor-core GEMM, 128x128 tile, double-buffered -----
__global__ void __launch_bounds__(256,2) gemm_tc(
        const float* __restrict__ A, int lda,
        const float* __restrict__ W, int ldw,
        const float* __restrict__ s, const float* __restrict__ bias,
        const float* __restrict__ Gb,
        float* __restrict__ C, int ldc, unsigned* gmax,
        int Kd, int Nd, float leak, int mode)
{
    __shared__ uint32_t As[2][128][20];
    __shared__ uint32_t Ws[2][128][20];
    int m0 = blockIdx.x*128, n0 = blockIdx.y*128;
    int tid = threadIdx.x, lane = tid & 31, w = tid >> 5;
    int gid = lane >> 2, tig = lane & 3;
    int wm = (w >> 2)*64, wn = (w & 3)*32;
    float4 acc[4][4];
    #pragma unroll
    for (int mt=0;mt<4;mt++)
        #pragma unroll
        for (int nt=0;nt<4;nt++) acc[mt][nt] = make_float4(0.f,0.f,0.f,0.f);

    int lr = tid >> 1, lq = (tid & 1)*8;
    const float* Ap = A + (size_t)(m0+lr)*lda + lq;
    const float* Wp = W + (size_t)(n0+lr)*ldw + lq;

    int nk = Kd >> 4;
    float4 ta0 = *(const float4*)(Ap);
    float4 ta1 = *(const float4*)(Ap + 4);
    float4 tw0 = *(const float4*)(Wp);
    float4 tw1 = *(const float4*)(Wp + 4);
    {
        uint4 ua0 = {f2tf(ta0.x),f2tf(ta0.y),f2tf(ta0.z),f2tf(ta0.w)};
        uint4 ua1 = {f2tf(ta1.x),f2tf(ta1.y),f2tf(ta1.z),f2tf(ta1.w)};
        uint4 uw0 = {f2tf(tw0.x),f2tf(tw0.y),f2tf(tw0.z),f2tf(tw0.w)};
        uint4 uw1 = {f2tf(tw1.x),f2tf(tw1.y),f2tf(tw1.z),f2tf(tw1.w)};
        *(uint4*)&As[0][lr][lq]   = ua0;
        *(uint4*)&As[0][lr][lq+4] = ua1;
        *(uint4*)&Ws[0][lr][lq]   = uw0;
        *(uint4*)&Ws[0][lr][lq+4] = uw1;
    }
    __syncthreads();

    for (int c = 0; c < nk; c++){
        int cur = c & 1;
        if (c + 1 < nk){
            int k0 = (c+1) << 4;
            ta0 = *(const float4*)(Ap + k0);
            ta1 = *(const float4*)(Ap + k0 + 4);
            tw0 = *(const float4*)(Wp + k0);
            tw1 = *(const float4*)(Wp + k0 + 4);
        }
        #pragma unroll
        for (int ks=0; ks<16; ks+=8){
            uint32_t bf[4][2];
            #pragma unroll
            for (int nt=0;nt<4;nt++){
                int n = wn + nt*8 + gid;
                bf[nt][0] = Ws[cur][n][ks+tig];
                bf[nt][1] = Ws[cur][n][ks+tig+4];
            }
            #pragma unroll
            for (int mt=0;mt<4;mt++){
                uint32_t af[4];
                int r = wm + mt*16;
                af[0] = As[cur][r+gid  ][ks+tig];
                af[1] = As[cur][r+gid+8][ks+tig];
                af[2] = As[cur][r+gid  ][ks+tig+4];
                af[3] = As[cur][r+gid+8][ks+tig+4];
                #pragma unroll
                for (int nt=0;nt<4;nt++) mma_tf32(acc[mt][nt], af, bf[nt]);
            }
        }
        if (c + 1 < nk){
            int nxt = cur ^ 1;
            uint4 ua0 = {f2tf(ta0.x),f2tf(ta0.y),f2tf(ta0.z),f2tf(ta0.w)};
            uint4 ua1 = {f2tf(ta1.x),f2tf(ta1.y),f2tf(ta1.z),f2tf(ta1.w)};
            uint4 uw0 = {f2tf(tw0.x),f2tf(tw0.y),f2tf(tw0.z),f2tf(tw0.w)};
            uint4 uw1 = {f2tf(tw1.x),f2tf(tw1.y),f2tf(tw1.z),f2tf(tw1.w)};
            *(uint4*)&As[nxt][lr][lq]   = ua0;
            *(uint4*)&As[nxt][lr][lq+4] = ua1;
            *(uint4*)&Ws[nxt][lr][lq]   = uw0;
            *(uint4*)&Ws[nxt][lr][lq+4] = uw1;
            __syncthreads();
        }
    }

    int b = m0 >> 12;
    if (mode == 0){
        #pragma unroll
        for (int mt=0;mt<4;mt++){
            int r0 = m0 + wm + mt*16 + gid;
            #pragma unroll
            for (int nt=0;nt<4;nt++){
                int cg = n0 + wn + nt*8 + 2*tig;
                float gx = 0.f, gy = 0.f;
                if (Gb){ gx = Gb[(size_t)b*Nd + cg]; gy = Gb[(size_t)b*Nd + cg + 1]; }
                float sx=1.f, sy=1.f, bx=0.f, by=0.f;
                if (s){ sx=s[cg]; sy=s[cg+1]; bx=bias[cg]; by=bias[cg+1]; }
                else if (bias){ bx=bias[cg]; by=bias[cg+1]; }
                float4 a = acc[mt][nt];
                float z0 = sx*(a.x+gx)+bx; z0 = z0>0.f? z0 : leak*z0;
                float z1 = sy*(a.y+gy)+by; z1 = z1>0.f? z1 : leak*z1;
                float z2 = sx*(a.z+gx)+bx; z2 = z2>0.f? z2 : leak*z2;
                float z3 = sy*(a.w+gy)+by; z3 = z3>0.f? z3 : leak*z3;
                *(float2*)&C[(size_t)r0*ldc + cg]     = make_float2(z0,z1);
                *(float2*)&C[(size_t)(r0+8)*ldc + cg] = make_float2(z2,z3);
            }
        }
    } else {
        #pragma unroll
        for (int nt=0;nt<4;nt++){
            int cg = n0 + wn + nt*8 + 2*tig;
            float sx=s[cg], bx=bias[cg], sy=s[cg+1], by=bias[cg+1];
            float mx=-FLT_MAX, my=-FLT_MAX;
            #pragma unroll
            for (int mt=0;mt<4;mt++){
                float4 a = acc[mt][nt];
                float z;
                z = sx*a.x+bx; z = z>0.f? z : leak*z; mx = fmaxf(mx,z);
                z = sx*a.z+bx; z = z>0.f? z : leak*z; mx = fmaxf(mx,z);
                z = sy*a.y+by; z = z>0.f? z : leak*z; my = fmaxf(my,z);
                z = sy*a.w+by; z = z>0.f? z : leak*z; my = fmaxf(my,z);
            }
            #pragma unroll
            for (int off=4; off<32; off<<=1){
                mx = fmaxf(mx, __shfl_xor_sync(0xffffffffu, mx, off));
                my = fmaxf(my, __shfl_xor_sync(0xffffffffu, my, off));
            }
            if (gid == 0){
                atomicMax(&gmax[b*1024 + cg],     enc_f(mx));
                atomicMax(&gmax[b*1024 + cg + 1], enc_f(my));
            }
        }
    }
}

// ---------------- small fp32 GEMM kept for conv9 (transposed store) --------
__global__ void __launch_bounds__(256,2) gemm128(
        const float* __restrict__ A, int lda,
        const float* __restrict__ W, int ldw,
        const float* __restrict__ bias,
        float* __restrict__ C, int Kd, int Nd)
{
    __shared__ float As[8][132];
    __shared__ float Ws[8][132];
    int m0 = blockIdx.x*128, n0 = blockIdx.y*128;
    int tid = threadIdx.x;
    int hr = tid >> 1;
    int kq = (tid & 1)*4;
    const float* Ap = A + (size_t)(m0 + hr)*lda + kq;
    bool wval = (n0 + hr) < Nd;
    const float* Wp = W + (size_t)(n0 + (wval ? hr : 0))*ldw + kq;
    int tx = tid & 15, ty = tid >> 4;
    float acc[8][8];
    #pragma unroll
    for (int i=0;i<8;i++)
        #pragma unroll
        for (int j=0;j<8;j++) acc[i][j]=0.f;

    for (int k0 = 0; k0 < Kd; k0 += 8){
        float4 a4 = *(const float4*)(Ap + k0);
        float4 w4 = wval ? *(const float4*)(Wp + k0) : make_float4(0.f,0.f,0.f,0.f);
        As[kq+0][hr]=a4.x; As[kq+1][hr]=a4.y; As[kq+2][hr]=a4.z; As[kq+3][hr]=a4.w;
        Ws[kq+0][hr]=w4.x; Ws[kq+1][hr]=w4.y; Ws[kq+2][hr]=w4.z; Ws[kq+3][hr]=w4.w;
        __syncthreads();
        #pragma unroll
        for (int k=0;k<8;k++){
            float4 a0 = *(const float4*)&As[k][ty*4];
            float4 a1 = *(const float4*)&As[k][64+ty*4];
            float4 w0 = *(const float4*)&Ws[k][tx*4];
            float4 w1 = *(const float4*)&Ws[k][64+tx*4];
            float ar[8] = {a0.x,a0.y,a0.z,a0.w,a1.x,a1.y,a1.z,a1.w};
            float wr[8] = {w0.x,w0.y,w0.z,w0.w,w1.x,w1.y,w1.z,w1.w};
            #pragma unroll
            for (int i=0;i<8;i++)
                #pragma unroll
                for (int j=0;j<8;j++) acc[i][j] += ar[i]*wr[j];
        }
        __syncthreads();
    }
    #pragma unroll
    for (int i=0;i<8;i++){
        int m = m0 + (i<4 ? ty*4+i : 64 + ty*4 + (i-4));
        int bb_ = m >> 12, nn = m & (NNN-1);
        #pragma unroll
        for (int j=0;j<8;j++){
            int n = n0 + (j<4 ? tx*4+j : 64 + tx*4 + (j-4));
            if (n < Nd){
                float z = acc[i][j] + (bias ? bias[n] : 0.f);
                C[((size_t)bb_*Nd + n)*NNN + nn] = z;
            }
        }
    }
}

// ---------------------------------------------------------------------------
extern "C" void kernel_launch(void* const* d_in, const int* in_sizes, int n_in,
                              void* d_out, int out_size){
    const float* x  = (const float*)d_in[0];
    const float* W1 = (const float*)d_in[1];
    const float* s1 = (const float*)d_in[2];
    const float* b1 = (const float*)d_in[3];
    const float* W2 = (const float*)d_in[4];
    const float* s2 = (const float*)d_in[5];
    const float* b2 = (const float*)d_in[6];
    const float* W3 = (const float*)d_in[7];
    const float* s3 = (const float*)d_in[8];
    const float* b3 = (const float*)d_in[9];
    const float* W4 = (const float*)d_in[10];
    const float* s4 = (const float*)d_in[11];
    const float* b4 = (const float*)d_in[12];
    const float* W5 = (const float*)d_in[13];
    const float* s5 = (const float*)d_in[14];
    const float* b5 = (const float*)d_in[15];
    const float* W6 = (const float*)d_in[16];
    const float* s6 = (const float*)d_in[17];
    const float* b6 = (const float*)d_in[18];
    const float* W7 = (const float*)d_in[19];
    const float* s7 = (const float*)d_in[20];
    const float* b7 = (const float*)d_in[21];
    const float* W8 = (const float*)d_in[22];
    const float* s8 = (const float*)d_in[23];
    const float* b8 = (const float*)d_in[24];
    const float* W9 = (const float*)d_in[25];
    const float* b9 = (const float*)d_in[26];
    float* out = (float*)d_out;

    float *nrm,*xcat,*PQ,*h7,*h8,*Wpq,*Gb; int* idx; unsigned* gmax;
    cudaGetSymbolAddress((void**)&nrm,  d_nrm);
    cudaGetSymbolAddress((void**)&idx,  d_idx);
    cudaGetSymbolAddress((void**)&xcat, d_xcat);
    cudaGetSymbolAddress((void**)&PQ,   d_PQ);
    cudaGetSymbolAddress((void**)&h7,   d_h7);
    cudaGetSymbolAddress((void**)&h8,   d_h8);
    cudaGetSymbolAddress((void**)&Wpq,  d_Wpq);
    cudaGetSymbolAddress((void**)&gmax, d_gmax);
    cudaGetSymbolAddress((void**)&Gb,   d_Gb);

    const float LK = 0.2f;
    const int edge_blocks = BN_/(EDGE_PPT*EDGE_ITER);
    const int knn_smem = KNN_Q*KQ_STRIDE*sizeof(unsigned);   // ~32.8KB

    static int knn_attr_done = 0;
    if (!knn_attr_done){
        cudaFuncSetAttribute(knn_radix2, cudaFuncAttributeMaxDynamicSharedMemorySize,
                             knn_smem);
        knn_attr_done = 1;
    }

    nrm_kernel<<<64,256>>>(x, nrm);
    knn_radix2<<<BN_/KNN_Q, 256, knn_smem>>>(x, nrm, idx);

    // stage 1: P/Q from coords, fused edge conv (conv1+conv2) + max_k -> x1
    pq1_kernel<<<4096,256>>>(x, W1, PQ);
    fused_edge_tc<<<edge_blocks,256>>>(PQ, s1, b1, W2, s2, b2, idx, xcat + 0, 192);

    // stage 2: P/Q = x1 * Wpq3, fused edge conv (conv3+conv4) + max_k -> x2
    wprep_kernel<<<32,256>>>(W3, Wpq);
    gemm_tc<<<dim3(128,1),256>>>(xcat, 192, Wpq, 64, nullptr, nullptr, nullptr,
                                 PQ, 128, nullptr, 64, 128, 1.f, 0);
    fused_edge_tc<<<edge_blocks,256>>>(PQ, s3, b3, W4, s4, b4, idx, xcat + 64, 192);

    // stage 3: P/Q = x2 * Wpq5, gather + lrelu + max_k -> x3
    wprep_kernel<<<32,256>>>(W5, Wpq);
    gemm_tc<<<dim3(128,1),256>>>(xcat + 64, 192, Wpq, 64, nullptr, nullptr, nullptr,
                                 PQ, 128, nullptr, 64, 128, 1.f, 0);
    maxgather_kernel<<<4096,256>>>(PQ, s5, b5, idx, xcat + 128, 192);

    // conv6 (192 -> 1024) with fused max over N (atomic)
    init_gmax<<<16,256>>>(gmax);
    gemm_tc<<<dim3(128,8),256>>>(xcat, 192, W6, 192, s6, b6, nullptr,
                                 nullptr, 0, gmax, 192, 1024, LK, 2);

    // per-batch bias from g through W7's first 1024 input channels
    gb_kernel<<<8,256>>>(gmax, W7, Gb);

    // conv7: xcat (192) through W7[:,1024:] + Gb  -> h7 (512)
    gemm_tc<<<dim3(128,4),256>>>(xcat, 192, W7 + 1024, 1216, s7, b7, Gb,
                                 h7, 512, nullptr, 192, 512, LK, 0);
    // conv8: 512 -> 256
    gemm_tc<<<dim3(128,2),256>>>(h7, 512, W8, 512, s8, b8, nullptr,
                                 h8, 256, nullptr, 512, 256, LK, 0);
    // conv9: 256 -> 63, + bias, transposed store
    gemm128<<<dim3(128,1),256>>>(h8, 256, W9, 256, b9, out, 256, 63);
}

// round 10
// speedup vs baseline: 1.1774x; 1.0947x over previous
#include <cuda_runtime.h>
#include <float.h>
#include <stdint.h>

#define NBB 4
#define NNN 4096
#define NKK 40
#define BN_ (NBB*NNN)            // 16384
#define BNK (BN_*NKK)            // 655360
#define EDGE_PPT 2               // points per tile (A = 96 rows)
#define EDGE_ITER 4              // tiles per block -> 8 points per block

// ---------------- static scratch ----------------
__device__ float    d_nrm[BN_];
__device__ int      d_idx[BNK];
__device__ float    d_xcat[(size_t)BN_*192];   // [x1|x2|x3] per point
__device__ float    d_PQ[(size_t)BN_*128];     // P (0..63) | Q (64..127)
__device__ float    d_h7[(size_t)BN_*512];
__device__ float    d_h8[(size_t)BN_*256];
__device__ float    d_Wpq[128*64];
__device__ unsigned d_gmax[NBB*1024];
__device__ float    d_Gb[NBB*512];

__device__ __forceinline__ unsigned enc_f(float f){
    unsigned u = __float_as_uint(f);
    return (u & 0x80000000u) ? ~u : (u | 0x80000000u);
}
__device__ __forceinline__ float dec_f(unsigned k){
    unsigned u = (k & 0x80000000u) ? (k & 0x7FFFFFFFu) : ~k;
    return __uint_as_float(u);
}
__device__ __forceinline__ uint32_t f2tf(float f){
    uint32_t r; asm("cvt.rna.tf32.f32 %0, %1;" : "=r"(r) : "f"(f)); return r;
}
__device__ __forceinline__ void mma_tf32(float4 &c, const uint32_t* a, const uint32_t* b){
    asm volatile("mma.sync.aligned.m16n8k8.row.col.f32.tf32.tf32.f32 "
        "{%0,%1,%2,%3}, {%4,%5,%6,%7}, {%8,%9}, {%0,%1,%2,%3};"
        : "+f"(c.x), "+f"(c.y), "+f"(c.z), "+f"(c.w)
        : "r"(a[0]), "r"(a[1]), "r"(a[2]), "r"(a[3]), "r"(b[0]), "r"(b[1]));
}

// ---------------- squared norms ----------------
__global__ void nrm_kernel(const float* __restrict__ x, float* __restrict__ nrm){
    int i = blockIdx.x*256 + threadIdx.x;
    if (i >= BN_) return;
    int b = i >> 12, n = i & (NNN-1);
    const float* xb = x + (size_t)b*3*NNN;
    float a = xb[n], c = xb[NNN+n], d = xb[2*NNN+n];
    nrm[i] = a*a + c*c + d*d;
}

// ---------------- kNN: 1 query/block radix select, vectorized sweeps -------
// Order-free top-40 is valid: every consumer of idx is a max over k.
__global__ void __launch_bounds__(256) knn_radix(const float* __restrict__ x,
                                                 const float* __restrict__ nrm,
                                                 int* __restrict__ idxo){
    __shared__ __align__(16) unsigned keys[NNN];   // 16KB
    __shared__ unsigned hist[256];
    __shared__ unsigned wtot[8];
    __shared__ unsigned sh_prefix;
    __shared__ int sh_remain, sh_shift, sh_done;
    __shared__ int cnt_hi, cnt_eq;

    int blk = blockIdx.x;
    int b = blk >> 12;
    int n = blk & (NNN-1);
    int tid = threadIdx.x;
    int w = tid >> 5, lane = tid & 31;
    unsigned lmask = (1u << lane) - 1u;
    const float* xb = x + (size_t)b*3*NNN;
    const float* nb = nrm + b*NNN;
    float qx = xb[n], qy = xb[NNN+n], qz = xb[2*NNN+n];
    float qn = nb[n];

    // distance phase: 4 candidates per thread per iter (float4 loads)
    for (int i0 = tid*4; i0 < NNN; i0 += 1024){
        float4 cx = *(const float4*)&xb[i0];
        float4 cy = *(const float4*)&xb[NNN + i0];
        float4 cz = *(const float4*)&xb[2*NNN + i0];
        float4 cn = *(const float4*)&nb[i0];
        uint4 kv;
        kv.x = enc_f(2.f*(qx*cx.x + qy*cy.x + qz*cz.x) - qn - cn.x);
        kv.y = enc_f(2.f*(qx*cx.y + qy*cy.y + qz*cz.y) - qn - cn.y);
        kv.z = enc_f(2.f*(qx*cx.z + qy*cy.z + qz*cz.z) - qn - cn.z);
        kv.w = enc_f(2.f*(qx*cx.w + qy*cy.w + qz*cz.w) - qn - cn.w);
        *(uint4*)&keys[i0] = kv;
    }
    if (tid == 0){ sh_prefix = 0; sh_remain = NKK; sh_done = 0; sh_shift = 0;
                   cnt_hi = 0; cnt_eq = 0; }
    __syncthreads();

    for (int pass = 0; pass < 4; pass++){
        int shift = 24 - 8*pass;
        hist[tid] = 0;
        __syncthreads();
        unsigned pfx = sh_prefix;
        int remain = sh_remain;
        for (int i0 = tid*4; i0 < NNN; i0 += 1024){
            uint4 kv = *(const uint4*)&keys[i0];
            unsigned ks[4] = {kv.x, kv.y, kv.z, kv.w};
            #pragma unroll
            for (int j = 0; j < 4; j++){
                unsigned k = ks[j];
                if (pass == 0){
                    unsigned bin = k >> 24;
                    unsigned mm = __match_any_sync(0xffffffffu, bin);
                    if (lane == __ffs(mm)-1) atomicAdd(&hist[bin], __popc(mm));
                } else {
                    bool pred = (k >> (shift + 8)) == pfx;
                    unsigned msk = __ballot_sync(0xffffffffu, pred);
                    if (pred){
                        unsigned bin = (k >> shift) & 255u;
                        unsigned mm = __match_any_sync(msk, bin);
                        if (lane == __ffs(mm)-1) atomicAdd(&hist[bin], __popc(mm));
                    }
                }
            }
        }
        __syncthreads();
        unsigned v = hist[tid];
        unsigned vv = v;
        #pragma unroll
        for (int off = 1; off < 32; off <<= 1){
            unsigned t = __shfl_down_sync(0xffffffffu, vv, off);
            if (lane + off < 32) vv += t;
        }
        if (lane == 0) wtot[w] = vv;
        __syncthreads();
        unsigned add = 0;
        for (int ww = w + 1; ww < 8; ww++) add += wtot[ww];
        unsigned suftid = vv + add;        // count of keys with bin >= tid
        unsigned above  = suftid - v;      // count with bin > tid
        if (suftid >= (unsigned)remain && above < (unsigned)remain){
            int newrem = remain - (int)above;
            sh_prefix = (pfx << 8) | (unsigned)tid;
            sh_remain = newrem;
            sh_shift  = shift;
            if ((unsigned)newrem == v) sh_done = 1;   // whole bin included
        }
        __syncthreads();
        if (sh_done) break;
    }

    unsigned thr = sh_prefix;              // prefix at granularity sh_shift
    int shift = sh_shift;
    int rem = sh_remain;
    int* out = idxo + (size_t)blk*NKK;

    // collect strictly-above keys (ballot-aggregated)
    for (int i0 = tid*4; i0 < NNN; i0 += 1024){
        uint4 kv = *(const uint4*)&keys[i0];
        unsigned ks[4] = {kv.x, kv.y, kv.z, kv.w};
        #pragma unroll
        for (int j = 0; j < 4; j++){
            bool hi = (ks[j] >> shift) > thr;
            unsigned m = __ballot_sync(0xffffffffu, hi);
            if (m){
                int ldr = __ffs(m)-1;
                unsigned base = 0;
                if (lane == ldr) base = atomicAdd(&cnt_hi, __popc(m));
                base = __shfl_sync(0xffffffffu, base, ldr);
                if (hi) out[base + __popc(m & lmask)] = i0 + j;
            }
        }
    }
    __syncthreads();
    int basehi = cnt_hi;                   // == 40 - rem
    // collect ties (first rem of them)
    for (int i0 = tid*4; i0 < NNN; i0 += 1024){
        uint4 kv = *(const uint4*)&keys[i0];
        unsigned ks[4] = {kv.x, kv.y, kv.z, kv.w};
        #pragma unroll
        for (int j = 0; j < 4; j++){
            bool eq = (ks[j] >> shift) == thr;
            unsigned m = __ballot_sync(0xffffffffu, eq);
            if (m){
                int ldr = __ffs(m)-1;
                unsigned base = 0;
                if (lane == ldr) base = atomicAdd(&cnt_eq, __popc(m));
                base = __shfl_sync(0xffffffffu, base, ldr);
                if (eq){
                    int pos = (int)(base + __popc(m & lmask));
                    if (pos < rem) out[basehi + pos] = i0 + j;
                }
            }
        }
    }
}

// ---------------- P/Q from coords (stage 1) --------------------------------
__global__ void pq1_kernel(const float* __restrict__ x, const float* __restrict__ W1,
                           float* __restrict__ PQ){
    int i = blockIdx.x*256 + threadIdx.x;
    int c = i & 63; int p = i >> 6;
    int b = p >> 12, n = p & (NNN-1);
    const float* xb = x + (size_t)b*3*NNN + n;
    float x0 = xb[0], x1 = xb[NNN], x2 = xb[2*NNN];
    const float* w = W1 + c*6;
    float pv = x0*w[0] + x1*w[1] + x2*w[2];
    float qv = x0*(w[3]-w[0]) + x1*(w[4]-w[1]) + x2*(w[5]-w[2]);
    PQ[(size_t)p*128 + c]      = pv;
    PQ[(size_t)p*128 + 64 + c] = qv;
}

// ---------------- weight prep: W (64x128) -> Wpq (128x64) ------------------
__global__ void wprep_kernel(const float* __restrict__ W, float* __restrict__ Wpq){
    int i = blockIdx.x*256 + threadIdx.x;
    int c = i & 63; int r = i >> 6;
    float v;
    if (r < 64) v = W[r*128 + c];
    else { int o = r - 64; v = W[o*128 + 64 + c] - W[o*128 + c]; }
    Wpq[r*64 + c] = v;
}

// ---------------- fused edge conv via tf32 mma, 2 points per tile ----------
__global__ void __launch_bounds__(256) fused_edge_tc(
        const float* __restrict__ PQ,
        const float* __restrict__ sa, const float* __restrict__ ba,
        const float* __restrict__ W2,
        const float* __restrict__ sb, const float* __restrict__ bb,
        const int* __restrict__ idx, float* __restrict__ xout, int ostride)
{
    __shared__ uint32_t As[96][68];
    __shared__ uint32_t Ws[64][68];
    __shared__ float qrow[2*64], sav[64], bav[64];
    __shared__ int js[2*40];
    int tid = threadIdx.x;
    int w = tid >> 5, lane = tid & 31;
    int gid = lane >> 2, tig = lane & 3;
    int pt = w >> 2, wn = w & 3;

    for (int i = tid; i < 4096; i += 256) Ws[i>>6][i&63] = f2tf(W2[i]);
    if (tid < 64){ sav[tid] = sa[tid]; bav[tid] = ba[tid]; }
    for (int i = tid; i < 8*68; i += 256){
        As[40 + i/68][i%68] = 0u;
        As[88 + i/68][i%68] = 0u;
    }

    int c0 = wn*16 + 2*tig;
    float se0 = sb[c0],   oe0 = bb[c0],   se1 = sb[c0+1],   oe1 = bb[c0+1];
    float se2 = sb[c0+8], oe2 = bb[c0+8], se3 = sb[c0+9],   oe3 = bb[c0+9];

    int p0 = blockIdx.x * (EDGE_PPT*EDGE_ITER);
    for (int it = 0; it < EDGE_ITER; it++){
        int pb = p0 + it*EDGE_PPT;
        if (tid < 128) qrow[tid] = PQ[(size_t)(pb + (tid>>6))*128 + 64 + (tid & 63)];
        if (tid < 80)  js[tid] = idx[(size_t)(pb + (tid>=40))*NKK + (tid>=40 ? tid-40 : tid)];
        __syncthreads();
        int base0 = ((pb)   >> 12) << 12;
        int base1 = ((pb+1) >> 12) << 12;
        for (int e = tid; e < 2*640; e += 256){
            int lpt = e / 640;
            int r = e - lpt*640;
            int k = r >> 4, c4 = r & 15;
            int bse = lpt ? base1 : base0;
            float4 v4 = *(const float4*)&PQ[((size_t)(bse + js[lpt*40 + k]))*128 + c4*4];
            float4 q4 = *(const float4*)&qrow[lpt*64 + c4*4];
            float4 sv = *(const float4*)&sav[c4*4];
            float4 bv = *(const float4*)&bav[c4*4];
            float z0 = sv.x*(v4.x+q4.x)+bv.x; z0 = z0>0.f? z0 : 0.2f*z0;
            float z1 = sv.y*(v4.y+q4.y)+bv.y; z1 = z1>0.f? z1 : 0.2f*z1;
            float z2 = sv.z*(v4.z+q4.z)+bv.z; z2 = z2>0.f? z2 : 0.2f*z2;
            float z3 = sv.w*(v4.w+q4.w)+bv.w; z3 = z3>0.f? z3 : 0.2f*z3;
            uint4 u = {f2tf(z0), f2tf(z1), f2tf(z2), f2tf(z3)};
            *(uint4*)&As[lpt*48 + k][c4*4] = u;
        }
        __syncthreads();

        float4 acc[3][2];
        #pragma unroll
        for (int mt=0;mt<3;mt++){ acc[mt][0]=make_float4(0.f,0.f,0.f,0.f);
                                  acc[mt][1]=make_float4(0.f,0.f,0.f,0.f); }
        int rbase = pt*48;
        #pragma unroll
        for (int k0=0;k0<64;k0+=8){
            uint32_t bf[2][2];
            #pragma unroll
            for (int nt=0;nt<2;nt++){
                bf[nt][0] = Ws[wn*16 + nt*8 + gid][k0+tig];
                bf[nt][1] = Ws[wn*16 + nt*8 + gid][k0+tig+4];
            }
            #pragma unroll
            for (int mt=0;mt<3;mt++){
                uint32_t af[4];
                int r = rbase + mt*16;
                af[0] = As[r+gid  ][k0+tig];
                af[1] = As[r+gid+8][k0+tig];
                af[2] = As[r+gid  ][k0+tig+4];
                af[3] = As[r+gid+8][k0+tig+4];
                mma_tf32(acc[mt][0], af, bf[0]);
                mma_tf32(acc[mt][1], af, bf[1]);
            }
        }
        float m00=-FLT_MAX, m01=-FLT_MAX, m10=-FLT_MAX, m11=-FLT_MAX;
        #pragma unroll
        for (int mt=0;mt<3;mt++){
            float z;
            z = se0*acc[mt][0].x + oe0; z = z>0.f? z : 0.2f*z; m00 = fmaxf(m00, z);
            z = se1*acc[mt][0].y + oe1; z = z>0.f? z : 0.2f*z; m01 = fmaxf(m01, z);
            z = se2*acc[mt][1].x + oe2; z = z>0.f? z : 0.2f*z; m10 = fmaxf(m10, z);
            z = se3*acc[mt][1].y + oe3; z = z>0.f? z : 0.2f*z; m11 = fmaxf(m11, z);
            if (mt < 2){
                z = se0*acc[mt][0].z + oe0; z = z>0.f? z : 0.2f*z; m00 = fmaxf(m00, z);
                z = se1*acc[mt][0].w + oe1; z = z>0.f? z : 0.2f*z; m01 = fmaxf(m01, z);
                z = se2*acc[mt][1].z + oe2; z = z>0.f? z : 0.2f*z; m10 = fmaxf(m10, z);
                z = se3*acc[mt][1].w + oe3; z = z>0.f? z : 0.2f*z; m11 = fmaxf(m11, z);
            }
        }
        #pragma unroll
        for (int off=4; off<32; off<<=1){
            m00 = fmaxf(m00, __shfl_xor_sync(0xffffffffu, m00, off));
            m01 = fmaxf(m01, __shfl_xor_sync(0xffffffffu, m01, off));
            m10 = fmaxf(m10, __shfl_xor_sync(0xffffffffu, m10, off));
            m11 = fmaxf(m11, __shfl_xor_sync(0xffffffffu, m11, off));
        }
        if (gid == 0){
            int p = pb + pt;
            xout[(size_t)p*ostride + c0]     = m00;
            xout[(size_t)p*ostride + c0+1]   = m01;
            xout[(size_t)p*ostride + c0+8]   = m10;
            xout[(size_t)p*ostride + c0+9]   = m11;
        }
        __syncthreads();
    }
}

// ---------------- stage 3: gather + BN/lrelu + max_k -----------------------
__global__ void maxgather_kernel(const float* __restrict__ PQ,
                                 const float* __restrict__ s, const float* __restrict__ bias,
                                 const int* __restrict__ idx,
                                 float* __restrict__ xout, int ostride){
    int i = blockIdx.x*256 + threadIdx.x;
    int o = i & 63, p = i >> 6; int b = p >> 12;
    float qv = PQ[(size_t)p*128 + 64 + o];
    float sc = s[o], bv = bias[o];
    const int* ip = idx + (size_t)p*NKK;
    size_t base = (size_t)(b << 12)*128;
    float m = -FLT_MAX;
    #pragma unroll 8
    for (int k=0;k<NKK;k++){
        float v = PQ[base + (size_t)ip[k]*128 + o] + qv;
        v = sc*v + bv;
        v = v>0.f? v : 0.2f*v;
        m = fmaxf(m, v);
    }
    xout[(size_t)p*ostride + o] = m;
}

__global__ void init_gmax(unsigned* g){
    int i = blockIdx.x*256 + threadIdx.x;
    if (i < NBB*1024) g[i] = 0u;
}

// ---------------- Gb[b][o] = sum_c g[b,c] * W7[o,c]  (c < 1024) ------------
__global__ void gb_kernel(const unsigned* __restrict__ gmax, const float* __restrict__ W7,
                          float* __restrict__ Gb){
    int i = blockIdx.x*256 + threadIdx.x;
    int o = i & 511; int b = i >> 9;
    const unsigned* gm = gmax + b*1024;
    const float* w = W7 + (size_t)o*1216;
    float a0=0.f,a1=0.f,a2=0.f,a3=0.f;
    for (int c=0;c<1024;c+=4){
        a0 += dec_f(gm[c+0])*w[c+0];
        a1 += dec_f(gm[c+1])*w[c+1];
        a2 += dec_f(gm[c+2])*w[c+2];
        a3 += dec_f(gm[c+3])*w[c+3];
    }
    Gb[(size_t)b*512 + o] = (a0+a1)+(a2+a3);
}

// ---------------- tf32 tensor-core GEMM, 128x128 tile, double-buffered -----
__global__ void __launch_bounds__(256,2) gemm_tc(
        const float* __restrict__ A, int lda,
        const float* __restrict__ W, int ldw,
        const float* __restrict__ s, const float* __restrict__ bias,
        const float* __restrict__ Gb,
        float* __restrict__ C, int ldc, unsigned* gmax,
        int Kd, int Nd, float leak, int mode)
{
    __shared__ uint32_t As[2][128][20];
    __shared__ uint32_t Ws[2][128][20];
    int m0 = blockIdx.x*128, n0 = blockIdx.y*128;
    int tid = threadIdx.x, lane = tid & 31, w = tid >> 5;
    int gid = lane >> 2, tig = lane & 3;
    int wm = (w >> 2)*64, wn = (w & 3)*32;
    float4 acc[4][4];
    #pragma unroll
    for (int mt=0;mt<4;mt++)
        #pragma unroll
        for (int nt=0;nt<4;nt++) acc[mt][nt] = make_float4(0.f,0.f,0.f,0.f);

    int lr = tid >> 1, lq = (tid & 1)*8;
    const float* Ap = A + (size_t)(m0+lr)*lda + lq;
    const float* Wp = W + (size_t)(n0+lr)*ldw + lq;

    int nk = Kd >> 4;
    float4 ta0 = *(const float4*)(Ap);
    float4 ta1 = *(const float4*)(Ap + 4);
    float4 tw0 = *(const float4*)(Wp);
    float4 tw1 = *(const float4*)(Wp + 4);
    {
        uint4 ua0 = {f2tf(ta0.x),f2tf(ta0.y),f2tf(ta0.z),f2tf(ta0.w)};
        uint4 ua1 = {f2tf(ta1.x),f2tf(ta1.y),f2tf(ta1.z),f2tf(ta1.w)};
        uint4 uw0 = {f2tf(tw0.x),f2tf(tw0.y),f2tf(tw0.z),f2tf(tw0.w)};
        uint4 uw1 = {f2tf(tw1.x),f2tf(tw1.y),f2tf(tw1.z),f2tf(tw1.w)};
        *(uint4*)&As[0][lr][lq]   = ua0;
        *(uint4*)&As[0][lr][lq+4] = ua1;
        *(uint4*)&Ws[0][lr][lq]   = uw0;
        *(uint4*)&Ws[0][lr][lq+4] = uw1;
    }
    __syncthreads();

    for (int c = 0; c < nk; c++){
        int cur = c & 1;
        if (c + 1 < nk){
            int k0 = (c+1) << 4;
            ta0 = *(const float4*)(Ap + k0);
            ta1 = *(const float4*)(Ap + k0 + 4);
            tw0 = *(const float4*)(Wp + k0);
            tw1 = *(const float4*)(Wp + k0 + 4);
        }
        #pragma unroll
        for (int ks=0; ks<16; ks+=8){
            uint32_t bf[4][2];
            #pragma unroll
            for (int nt=0;nt<4;nt++){
                int n = wn + nt*8 + gid;
                bf[nt][0] = Ws[cur][n][ks+tig];
                bf[nt][1] = Ws[cur][n][ks+tig+4];
            }
            #pragma unroll
            for (int mt=0;mt<4;mt++){
                uint32_t af[4];
                int r = wm + mt*16;
                af[0] = As[cur][r+gid  ][ks+tig];
                af[1] = As[cur][r+gid+8][ks+tig];
                af[2] = As[cur][r+gid  ][ks+tig+4];
                af[3] = As[cur][r+gid+8][ks+tig+4];
                #pragma unroll
                for (int nt=0;nt<4;nt++) mma_tf32(acc[mt][nt], af, bf[nt]);
            }
        }
        if (c + 1 < nk){
            int nxt = cur ^ 1;
            uint4 ua0 = {f2tf(ta0.x),f2tf(ta0.y),f2tf(ta0.z),f2tf(ta0.w)};
            uint4 ua1 = {f2tf(ta1.x),f2tf(ta1.y),f2tf(ta1.z),f2tf(ta1.w)};
            uint4 uw0 = {f2tf(tw0.x),f2tf(tw0.y),f2tf(tw0.z),f2tf(tw0.w)};
            uint4 uw1 = {f2tf(tw1.x),f2tf(tw1.y),f2tf(tw1.z),f2tf(tw1.w)};
            *(uint4*)&As[nxt][lr][lq]   = ua0;
            *(uint4*)&As[nxt][lr][lq+4] = ua1;
            *(uint4*)&Ws[nxt][lr][lq]   = uw0;
            *(uint4*)&Ws[nxt][lr][lq+4] = uw1;
            __syncthreads();
        }
    }

    int b = m0 >> 12;
    if (mode == 0){
        #pragma unroll
        for (int mt=0;mt<4;mt++){
            int r0 = m0 + wm + mt*16 + gid;
            #pragma unroll
            for (int nt=0;nt<4;nt++){
                int cg = n0 + wn + nt*8 + 2*tig;
                float gx = 0.f, gy = 0.f;
                if (Gb){ gx = Gb[(size_t)b*Nd + cg]; gy = Gb[(size_t)b*Nd + cg + 1]; }
                float sx=1.f, sy=1.f, bx=0.f, by=0.f;
                if (s){ sx=s[cg]; sy=s[cg+1]; bx=bias[cg]; by=bias[cg+1]; }
                else if (bias){ bx=bias[cg]; by=bias[cg+1]; }
                float4 a = acc[mt][nt];
                float z0 = sx*(a.x+gx)+bx; z0 = z0>0.f? z0 : leak*z0;
                float z1 = sy*(a.y+gy)+by; z1 = z1>0.f? z1 : leak*z1;
                float z2 = sx*(a.z+gx)+bx; z2 = z2>0.f? z2 : leak*z2;
                float z3 = sy*(a.w+gy)+by; z3 = z3>0.f? z3 : leak*z3;
                *(float2*)&C[(size_t)r0*ldc + cg]     = make_float2(z0,z1);
                *(float2*)&C[(size_t)(r0+8)*ldc + cg] = make_float2(z2,z3);
            }
        }
    } else {
        #pragma unroll
        for (int nt=0;nt<4;nt++){
            int cg = n0 + wn + nt*8 + 2*tig;
            float sx=s[cg], bx=bias[cg], sy=s[cg+1], by=bias[cg+1];
            float mx=-FLT_MAX, my=-FLT_MAX;
            #pragma unroll
            for (int mt=0;mt<4;mt++){
                float4 a = acc[mt][nt];
                float z;
                z = sx*a.x+bx; z = z>0.f? z : leak*z; mx = fmaxf(mx,z);
                z = sx*a.z+bx; z = z>0.f? z : leak*z; mx = fmaxf(mx,z);
                z = sy*a.y+by; z = z>0.f? z : leak*z; my = fmaxf(my,z);
                z = sy*a.w+by; z = z>0.f? z : leak*z; my = fmaxf(my,z);
            }
            #pragma unroll
            for (int off=4; off<32; off<<=1){
                mx = fmaxf(mx, __shfl_xor_sync(0xffffffffu, mx, off));
                my = fmaxf(my, __shfl_xor_sync(0xffffffffu, my, off));
            }
            if (gid == 0){
                atomicMax(&gmax[b*1024 + cg],     enc_f(mx));
                atomicMax(&gmax[b*1024 + cg + 1], enc_f(my));
            }
        }
    }
}

// ---------------- small fp32 GEMM kept for conv9 (transposed store) --------
__global__ void __launch_bounds__(256,2) gemm128(
        const float* __restrict__ A, int lda,
        const float* __restrict__ W, int ldw,
        const float* __restrict__ bias,
        float* __restrict__ C, int Kd, int Nd)
{
    __shared__ float As[8][132];
    __shared__ float Ws[8][132];
    int m0 = blockIdx.x*128, n0 = blockIdx.y*128;
    int tid = threadIdx.x;
    int hr = tid >> 1;
    int kq = (tid & 1)*4;
    const float* Ap = A + (size_t)(m0 + hr)*lda + kq;
    bool wval = (n0 + hr) < Nd;
    const float* Wp = W + (size_t)(n0 + (wval ? hr : 0))*ldw + kq;
    int tx = tid & 15, ty = tid >> 4;
    float acc[8][8];
    #pragma unroll
    for (int i=0;i<8;i++)
        #pragma unroll
        for (int j=0;j<8;j++) acc[i][j]=0.f;

    for (int k0 = 0; k0 < Kd; k0 += 8){
        float4 a4 = *(const float4*)(Ap + k0);
        float4 w4 = wval ? *(const float4*)(Wp + k0) : make_float4(0.f,0.f,0.f,0.f);
        As[kq+0][hr]=a4.x; As[kq+1][hr]=a4.y; As[kq+2][hr]=a4.z; As[kq+3][hr]=a4.w;
        Ws[kq+0][hr]=w4.x; Ws[kq+1][hr]=w4.y; Ws[kq+2][hr]=w4.z; Ws[kq+3][hr]=w4.w;
        __syncthreads();
        #pragma unroll
        for (int k=0;k<8;k++){
            float4 a0 = *(const float4*)&As[k][ty*4];
            float4 a1 = *(const float4*)&As[k][64+ty*4];
            float4 w0 = *(const float4*)&Ws[k][tx*4];
            float4 w1 = *(const float4*)&Ws[k][64+tx*4];
            float ar[8] = {a0.x,a0.y,a0.z,a0.w,a1.x,a1.y,a1.z,a1.w};
            float wr[8] = {w0.x,w0.y,w0.z,w0.w,w1.x,w1.y,w1.z,w1.w};
            #pragma unroll
            for (int i=0;i<8;i++)
                #pragma unroll
                for (int j=0;j<8;j++) acc[i][j] += ar[i]*wr[j];
        }
        __syncthreads();
    }
    #pragma unroll
    for (int i=0;i<8;i++){
        int m = m0 + (i<4 ? ty*4+i : 64 + ty*4 + (i-4));
        int bb_ = m >> 12, nn = m & (NNN-1);
        #pragma unroll
        for (int j=0;j<8;j++){
            int n = n0 + (j<4 ? tx*4+j : 64 + tx*4 + (j-4));
            if (n < Nd){
                float z = acc[i][j] + (bias ? bias[n] : 0.f);
                C[((size_t)bb_*Nd + n)*NNN + nn] = z;
            }
        }
    }
}

// ---------------------------------------------------------------------------
extern "C" void kernel_launch(void* const* d_in, const int* in_sizes, int n_in,
                              void* d_out, int out_size){
    const float* x  = (const float*)d_in[0];
    const float* W1 = (const float*)d_in[1];
    const float* s1 = (const float*)d_in[2];
    const float* b1 = (const float*)d_in[3];
    const float* W2 = (const float*)d_in[4];
    const float* s2 = (const float*)d_in[5];
    const float* b2 = (const float*)d_in[6];
    const float* W3 = (const float*)d_in[7];
    const float* s3 = (const float*)d_in[8];
    const float* b3 = (const float*)d_in[9];
    const float* W4 = (const float*)d_in[10];
    const float* s4 = (const float*)d_in[11];
    const float* b4 = (const float*)d_in[12];
    const float* W5 = (const float*)d_in[13];
    const float* s5 = (const float*)d_in[14];
    const float* b5 = (const float*)d_in[15];
    const float* W6 = (const float*)d_in[16];
    const float* s6 = (const float*)d_in[17];
    const float* b6 = (const float*)d_in[18];
    const float* W7 = (const float*)d_in[19];
    const float* s7 = (const float*)d_in[20];
    const float* b7 = (const float*)d_in[21];
    const float* W8 = (const float*)d_in[22];
    const float* s8 = (const float*)d_in[23];
    const float* b8 = (const float*)d_in[24];
    const float* W9 = (const float*)d_in[25];
    const float* b9 = (const float*)d_in[26];
    float* out = (float*)d_out;

    float *nrm,*xcat,*PQ,*h7,*h8,*Wpq,*Gb; int* idx; unsigned* gmax;
    cudaGetSymbolAddress((void**)&nrm,  d_nrm);
    cudaGetSymbolAddress((void**)&idx,  d_idx);
    cudaGetSymbolAddress((void**)&xcat, d_xcat);
    cudaGetSymbolAddress((void**)&PQ,   d_PQ);
    cudaGetSymbolAddress((void**)&h7,   d_h7);
    cudaGetSymbolAddress((void**)&h8,   d_h8);
    cudaGetSymbolAddress((void**)&Wpq,  d_Wpq);
    cudaGetSymbolAddress((void**)&gmax, d_gmax);
    cudaGetSymbolAddress((void**)&Gb,   d_Gb);

    const float LK = 0.2f;
    const int edge_blocks = BN_/(EDGE_PPT*EDGE_ITER);

    nrm_kernel<<<64,256>>>(x, nrm);
    knn_radix<<<BN_,256>>>(x, nrm, idx);

    // stage 1: P/Q from coords, fused edge conv (conv1+conv2) + max_k -> x1
    pq1_kernel<<<4096,256>>>(x, W1, PQ);
    fused_edge_tc<<<edge_blocks,256>>>(PQ, s1, b1, W2, s2, b2, idx, xcat + 0, 192);

    // stage 2: P/Q = x1 * Wpq3, fused edge conv (conv3+conv4) + max_k -> x2
    wprep_kernel<<<32,256>>>(W3, Wpq);
    gemm_tc<<<dim3(128,1),256>>>(xcat, 192, Wpq, 64, nullptr, nullptr, nullptr,
                                 PQ, 128, nullptr, 64, 128, 1.f, 0);
    fused_edge_tc<<<edge_blocks,256>>>(PQ, s3, b3, W4, s4, b4, idx, xcat + 64, 192);

    // stage 3: P/Q = x2 * Wpq5, gather + lrelu + max_k -> x3
    wprep_kernel<<<32,256>>>(W5, Wpq);
    gemm_tc<<<dim3(128,1),256>>>(xcat + 64, 192, Wpq, 64, nullptr, nullptr, nullptr,
                                 PQ, 128, nullptr, 64, 128, 1.f, 0);
    maxgather_kernel<<<4096,256>>>(PQ, s5, b5, idx, xcat + 128, 192);

    // conv6 (192 -> 1024) with fused max over N (atomic)
    init_gmax<<<16,256>>>(gmax);
    gemm_tc<<<dim3(128,8),256>>>(xcat, 192, W6, 192, s6, b6, nullptr,
                                 nullptr, 0, gmax, 192, 1024, LK, 2);

    // per-batch bias from g through W7's first 1024 input channels
    gb_kernel<<<8,256>>>(gmax, W7, Gb);

    // conv7: xcat (192) through W7[:,1024:] + Gb  -> h7 (512)
    gemm_tc<<<dim3(128,4),256>>>(xcat, 192, W7 + 1024, 1216, s7, b7, Gb,
                                 h7, 512, nullptr, 192, 512, LK, 0);
    // conv8: 512 -> 256
    gemm_tc<<<dim3(128,2),256>>>(h7, 512, W8, 512, s8, b8, nullptr,
                                 h8, 256, nullptr, 512, 256, LK, 0);
    // conv9: 256 -> 63, + bias, transposed store
    gemm128<<<dim3(128,1),256>>>(h8, 256, W9, 256, b9, out, 256, 63);
}

// round 11
// speedup vs baseline: 1.3552x; 1.1510x over previous
#include <cuda_runtime.h>
#include <cuda_fp16.h>
#include <float.h>
#include <stdint.h>

#define NBB 4
#define NNN 4096
#define NKK 40
#define BN_ (NBB*NNN)            // 16384
#define BNK (BN_*NKK)            // 655360
#define EDGE_PPT 2               // points per tile (A = 96 rows)
#define EDGE_ITER 4              // tiles per block -> 8 points per block

// ---------------- static scratch ----------------
__device__ int      d_idx[BNK];
__device__ float    d_xcat[(size_t)BN_*192];   // [x1|x2|x3] per point
__device__ float    d_PQ[(size_t)BN_*128];     // P (0..63) | Q (64..127)
__device__ float    d_h7[(size_t)BN_*512];
__device__ float    d_h8[(size_t)BN_*256];
__device__ float    d_Wpq[128*64];
__device__ unsigned d_gmax[NBB*1024];
__device__ float    d_Gb[NBB*512];

__device__ __forceinline__ unsigned enc_f(float f){
    unsigned u = __float_as_uint(f);
    return (u & 0x80000000u) ? ~u : (u | 0x80000000u);
}
__device__ __forceinline__ float dec_f(unsigned k){
    unsigned u = (k & 0x80000000u) ? (k & 0x7FFFFFFFu) : ~k;
    return __uint_as_float(u);
}
__device__ __forceinline__ uint32_t pack_h2(float a, float b){
    __half2 h = __floats2half2_rn(a, b);       // .x = a (low), .y = b (high)
    return *(uint32_t*)&h;
}
// m16n8k16 fp16 mma, fp32 accum
__device__ __forceinline__ void mma_f16(float4 &c, const uint32_t* a, const uint32_t* b){
    asm volatile("mma.sync.aligned.m16n8k16.row.col.f32.f16.f16.f32 "
        "{%0,%1,%2,%3}, {%4,%5,%6,%7}, {%8,%9}, {%0,%1,%2,%3};"
        : "+f"(c.x), "+f"(c.y), "+f"(c.z), "+f"(c.w)
        : "r"(a[0]), "r"(a[1]), "r"(a[2]), "r"(a[3]), "r"(b[0]), "r"(b[1]));
}

// ---------------- kNN: 1 query/block radix select, norms inline ------------
// Order-free top-40 is valid: every consumer of idx is a max over k.
__global__ void __launch_bounds__(256) knn_radix(const float* __restrict__ x,
                                                 int* __restrict__ idxo){
    __shared__ __align__(16) unsigned keys[NNN];   // 16KB
    __shared__ unsigned hist[256];
    __shared__ unsigned wtot[8];
    __shared__ unsigned sh_prefix;
    __shared__ int sh_remain, sh_shift, sh_done;
    __shared__ int cnt_hi, cnt_eq;

    int blk = blockIdx.x;
    int b = blk >> 12;
    int n = blk & (NNN-1);
    int tid = threadIdx.x;
    int w = tid >> 5, lane = tid & 31;
    unsigned lmask = (1u << lane) - 1u;
    const float* xb = x + (size_t)b*3*NNN;
    float qx = xb[n], qy = xb[NNN+n], qz = xb[2*NNN+n];
    float qn = qx*qx + qy*qy + qz*qz;

    // distance phase: 4 candidates per thread per iter, norms computed inline
    for (int i0 = tid*4; i0 < NNN; i0 += 1024){
        float4 cx = *(const float4*)&xb[i0];
        float4 cy = *(const float4*)&xb[NNN + i0];
        float4 cz = *(const float4*)&xb[2*NNN + i0];
        uint4 kv;
        kv.x = enc_f(2.f*(qx*cx.x + qy*cy.x + qz*cz.x) - qn - (cx.x*cx.x + cy.x*cy.x + cz.x*cz.x));
        kv.y = enc_f(2.f*(qx*cx.y + qy*cy.y + qz*cz.y) - qn - (cx.y*cx.y + cy.y*cy.y + cz.y*cz.y));
        kv.z = enc_f(2.f*(qx*cx.z + qy*cy.z + qz*cz.z) - qn - (cx.z*cx.z + cy.z*cy.z + cz.z*cz.z));
        kv.w = enc_f(2.f*(qx*cx.w + qy*cy.w + qz*cz.w) - qn - (cx.w*cx.w + cy.w*cy.w + cz.w*cz.w));
        *(uint4*)&keys[i0] = kv;
    }
    if (tid == 0){ sh_prefix = 0; sh_remain = NKK; sh_done = 0; sh_shift = 0;
                   cnt_hi = 0; cnt_eq = 0; }
    __syncthreads();

    for (int pass = 0; pass < 4; pass++){
        int shift = 24 - 8*pass;
        hist[tid] = 0;
        __syncthreads();
        unsigned pfx = sh_prefix;
        int remain = sh_remain;
        for (int i0 = tid*4; i0 < NNN; i0 += 1024){
            uint4 kv = *(const uint4*)&keys[i0];
            unsigned ks[4] = {kv.x, kv.y, kv.z, kv.w};
            #pragma unroll
            for (int j = 0; j < 4; j++){
                unsigned k = ks[j];
                if (pass == 0){
                    unsigned bin = k >> 24;
                    unsigned mm = __match_any_sync(0xffffffffu, bin);
                    if (lane == __ffs(mm)-1) atomicAdd(&hist[bin], __popc(mm));
                } else {
                    bool pred = (k >> (shift + 8)) == pfx;
                    unsigned msk = __ballot_sync(0xffffffffu, pred);
                    if (pred){
                        unsigned bin = (k >> shift) & 255u;
                        unsigned mm = __match_any_sync(msk, bin);
                        if (lane == __ffs(mm)-1) atomicAdd(&hist[bin], __popc(mm));
                    }
                }
            }
        }
        __syncthreads();
        unsigned v = hist[tid];
        unsigned vv = v;
        #pragma unroll
        for (int off = 1; off < 32; off <<= 1){
            unsigned t = __shfl_down_sync(0xffffffffu, vv, off);
            if (lane + off < 32) vv += t;
        }
        if (lane == 0) wtot[w] = vv;
        __syncthreads();
        unsigned add = 0;
        for (int ww = w + 1; ww < 8; ww++) add += wtot[ww];
        unsigned suftid = vv + add;
        unsigned above  = suftid - v;
        if (suftid >= (unsigned)remain && above < (unsigned)remain){
            int newrem = remain - (int)above;
            sh_prefix = (pfx << 8) | (unsigned)tid;
            sh_remain = newrem;
            sh_shift  = shift;
            if ((unsigned)newrem == v) sh_done = 1;
        }
        __syncthreads();
        if (sh_done) break;
    }

    unsigned thr = sh_prefix;
    int shift = sh_shift;
    int rem = sh_remain;
    int* out = idxo + (size_t)blk*NKK;

    for (int i0 = tid*4; i0 < NNN; i0 += 1024){
        uint4 kv = *(const uint4*)&keys[i0];
        unsigned ks[4] = {kv.x, kv.y, kv.z, kv.w};
        #pragma unroll
        for (int j = 0; j < 4; j++){
            bool hi = (ks[j] >> shift) > thr;
            unsigned m = __ballot_sync(0xffffffffu, hi);
            if (m){
                int ldr = __ffs(m)-1;
                unsigned base = 0;
                if (lane == ldr) base = atomicAdd(&cnt_hi, __popc(m));
                base = __shfl_sync(0xffffffffu, base, ldr);
                if (hi) out[base + __popc(m & lmask)] = i0 + j;
            }
        }
    }
    __syncthreads();
    int basehi = cnt_hi;
    for (int i0 = tid*4; i0 < NNN; i0 += 1024){
        uint4 kv = *(const uint4*)&keys[i0];
        unsigned ks[4] = {kv.x, kv.y, kv.z, kv.w};
        #pragma unroll
        for (int j = 0; j < 4; j++){
            bool eq = (ks[j] >> shift) == thr;
            unsigned m = __ballot_sync(0xffffffffu, eq);
            if (m){
                int ldr = __ffs(m)-1;
                unsigned base = 0;
                if (lane == ldr) base = atomicAdd(&cnt_eq, __popc(m));
                base = __shfl_sync(0xffffffffu, base, ldr);
                if (eq){
                    int pos = (int)(base + __popc(m & lmask));
                    if (pos < rem) out[basehi + pos] = i0 + j;
                }
            }
        }
    }
}

// ---------------- P/Q from coords (stage 1) --------------------------------
__global__ void pq1_kernel(const float* __restrict__ x, const float* __restrict__ W1,
                           float* __restrict__ PQ){
    int i = blockIdx.x*256 + threadIdx.x;
    int c = i & 63; int p = i >> 6;
    int b = p >> 12, n = p & (NNN-1);
    const float* xb = x + (size_t)b*3*NNN + n;
    float x0 = xb[0], x1 = xb[NNN], x2 = xb[2*NNN];
    const float* w = W1 + c*6;
    float pv = x0*w[0] + x1*w[1] + x2*w[2];
    float qv = x0*(w[3]-w[0]) + x1*(w[4]-w[1]) + x2*(w[5]-w[2]);
    PQ[(size_t)p*128 + c]      = pv;
    PQ[(size_t)p*128 + 64 + c] = qv;
}

// ---------------- weight prep: W (64x128) -> Wpq (128x64) ------------------
__global__ void wprep_kernel(const float* __restrict__ W, float* __restrict__ Wpq){
    int i = blockIdx.x*256 + threadIdx.x;
    int c = i & 63; int r = i >> 6;
    float v;
    if (r < 64) v = W[r*128 + c];
    else { int o = r - 64; v = W[o*128 + 64 + c] - W[o*128 + c]; }
    Wpq[r*64 + c] = v;
}

// ---------------- fused edge conv via fp16 mma, 2 points per tile ----------
// A packed half2 along k: As[row][kpack], stride 36 words (conflict-free).
__global__ void __launch_bounds__(256) fused_edge_tc(
        const float* __restrict__ PQ,
        const float* __restrict__ sa, const float* __restrict__ ba,
        const float* __restrict__ W2,
        const float* __restrict__ sb, const float* __restrict__ bb,
        const int* __restrict__ idx, float* __restrict__ xout, int ostride)
{
    __shared__ uint32_t As[96][36];       // 96 rows x 32 packed k (pad 4)
    __shared__ uint32_t Ws[64][36];       // 64 out-ch x 32 packed k
    __shared__ float qrow[2*64], sav[64], bav[64];
    __shared__ int js[2*40];
    int tid = threadIdx.x;
    int w = tid >> 5, lane = tid & 31;
    int gid = lane >> 2, tig = lane & 3;
    int pt = w >> 2, wn = w & 3;

    // W2: [64][64] -> packed pairs along input dim
    const float2* W2v = (const float2*)W2;
    for (int i = tid; i < 2048; i += 256){
        int nn = i >> 5, jc = i & 31;
        float2 wv = W2v[nn*32 + jc];
        Ws[nn][jc] = pack_h2(wv.x, wv.y);
    }
    if (tid < 64){ sav[tid] = sa[tid]; bav[tid] = ba[tid]; }
    // zero pad rows (40..47, 88..95) once
    for (int i = tid; i < 8*36; i += 256){
        As[40 + i/36][i%36] = 0u;
        As[88 + i/36][i%36] = 0u;
    }

    int c0 = wn*16 + 2*tig;
    float se0 = sb[c0],   oe0 = bb[c0],   se1 = sb[c0+1],   oe1 = bb[c0+1];
    float se2 = sb[c0+8], oe2 = bb[c0+8], se3 = sb[c0+9],   oe3 = bb[c0+9];

    int p0 = blockIdx.x * (EDGE_PPT*EDGE_ITER);
    for (int it = 0; it < EDGE_ITER; it++){
        int pb = p0 + it*EDGE_PPT;
        if (tid < 128) qrow[tid] = PQ[(size_t)(pb + (tid>>6))*128 + 64 + (tid & 63)];
        if (tid < 80)  js[tid] = idx[(size_t)(pb + (tid>=40))*NKK + (tid>=40 ? tid-40 : tid)];
        __syncthreads();
        int base0 = ((pb)   >> 12) << 12;
        int base1 = ((pb+1) >> 12) << 12;
        for (int e = tid; e < 2*640; e += 256){
            int lpt = e / 640;
            int r = e - lpt*640;
            int k = r >> 4, c4 = r & 15;
            int bse = lpt ? base1 : base0;
            float4 v4 = *(const float4*)&PQ[((size_t)(bse + js[lpt*40 + k]))*128 + c4*4];
            float4 q4 = *(const float4*)&qrow[lpt*64 + c4*4];
            float4 sv = *(const float4*)&sav[c4*4];
            float4 bv = *(const float4*)&bav[c4*4];
            float z0 = sv.x*(v4.x+q4.x)+bv.x; z0 = z0>0.f? z0 : 0.2f*z0;
            float z1 = sv.y*(v4.y+q4.y)+bv.y; z1 = z1>0.f? z1 : 0.2f*z1;
            float z2 = sv.z*(v4.z+q4.z)+bv.z; z2 = z2>0.f? z2 : 0.2f*z2;
            float z3 = sv.w*(v4.w+q4.w)+bv.w; z3 = z3>0.f? z3 : 0.2f*z3;
            uint2 u = {pack_h2(z0,z1), pack_h2(z2,z3)};
            *(uint2*)&As[lpt*48 + k][c4*2] = u;
        }
        __syncthreads();

        float4 acc[3][2];
        #pragma unroll
        for (int mt=0;mt<3;mt++){ acc[mt][0]=make_float4(0.f,0.f,0.f,0.f);
                                  acc[mt][1]=make_float4(0.f,0.f,0.f,0.f); }
        int rbase = pt*48;
        #pragma unroll
        for (int kt=0;kt<4;kt++){          // 4 x k16
            int k0p = kt*8;
            uint32_t bf[2][2];
            #pragma unroll
            for (int nt=0;nt<2;nt++){
                bf[nt][0] = Ws[wn*16 + nt*8 + gid][k0p+tig];
                bf[nt][1] = Ws[wn*16 + nt*8 + gid][k0p+tig+4];
            }
            #pragma unroll
            for (int mt=0;mt<3;mt++){
                uint32_t af[4];
                int r = rbase + mt*16;
                af[0] = As[r+gid  ][k0p+tig];
                af[1] = As[r+gid+8][k0p+tig];
                af[2] = As[r+gid  ][k0p+tig+4];
                af[3] = As[r+gid+8][k0p+tig+4];
                mma_f16(acc[mt][0], af, bf[0]);
                mma_f16(acc[mt][1], af, bf[1]);
            }
        }
        float m00=-FLT_MAX, m01=-FLT_MAX, m10=-FLT_MAX, m11=-FLT_MAX;
        #pragma unroll
        for (int mt=0;mt<3;mt++){
            float z;
            z = se0*acc[mt][0].x + oe0; z = z>0.f? z : 0.2f*z; m00 = fmaxf(m00, z);
            z = se1*acc[mt][0].y + oe1; z = z>0.f? z : 0.2f*z; m01 = fmaxf(m01, z);
            z = se2*acc[mt][1].x + oe2; z = z>0.f? z : 0.2f*z; m10 = fmaxf(m10, z);
            z = se3*acc[mt][1].y + oe3; z = z>0.f? z : 0.2f*z; m11 = fmaxf(m11, z);
            if (mt < 2){
                z = se0*acc[mt][0].z + oe0; z = z>0.f? z : 0.2f*z; m00 = fmaxf(m00, z);
                z = se1*acc[mt][0].w + oe1; z = z>0.f? z : 0.2f*z; m01 = fmaxf(m01, z);
                z = se2*acc[mt][1].z + oe2; z = z>0.f? z : 0.2f*z; m10 = fmaxf(m10, z);
                z = se3*acc[mt][1].w + oe3; z = z>0.f? z : 0.2f*z; m11 = fmaxf(m11, z);
            }
        }
        #pragma unroll
        for (int off=4; off<32; off<<=1){
            m00 = fmaxf(m00, __shfl_xor_sync(0xffffffffu, m00, off));
            m01 = fmaxf(m01, __shfl_xor_sync(0xffffffffu, m01, off));
            m10 = fmaxf(m10, __shfl_xor_sync(0xffffffffu, m10, off));
            m11 = fmaxf(m11, __shfl_xor_sync(0xffffffffu, m11, off));
        }
        if (gid == 0){
            int p = pb + pt;
            xout[(size_t)p*ostride + c0]     = m00;
            xout[(size_t)p*ostride + c0+1]   = m01;
            xout[(size_t)p*ostride + c0+8]   = m10;
            xout[(size_t)p*ostride + c0+9]   = m11;
        }
        __syncthreads();
    }
}

// ---------------- stage 3: gather + BN/lrelu + max_k (float4) --------------
__global__ void maxgather_kernel(const float* __restrict__ PQ,
                                 const float* __restrict__ s, const float* __restrict__ bias,
                                 const int* __restrict__ idx,
                                 float* __restrict__ xout, int ostride){
    int i = blockIdx.x*256 + threadIdx.x;   // BN_*16
    int c4 = i & 15, p = i >> 4; int b = p >> 12;
    float4 q = *(const float4*)&PQ[(size_t)p*128 + 64 + c4*4];
    float4 sc = *(const float4*)&s[c4*4];
    float4 bv = *(const float4*)&bias[c4*4];
    const int* ip = idx + (size_t)p*NKK;
    size_t base = (size_t)(b << 12)*128;
    float4 m = make_float4(-FLT_MAX,-FLT_MAX,-FLT_MAX,-FLT_MAX);
    #pragma unroll 8
    for (int k=0;k<NKK;k++){
        float4 v = *(const float4*)&PQ[base + (size_t)ip[k]*128 + c4*4];
        float z;
        z = sc.x*(v.x+q.x)+bv.x; z = z>0.f? z : 0.2f*z; m.x = fmaxf(m.x, z);
        z = sc.y*(v.y+q.y)+bv.y; z = z>0.f? z : 0.2f*z; m.y = fmaxf(m.y, z);
        z = sc.z*(v.z+q.z)+bv.z; z = z>0.f? z : 0.2f*z; m.z = fmaxf(m.z, z);
        z = sc.w*(v.w+q.w)+bv.w; z = z>0.f? z : 0.2f*z; m.w = fmaxf(m.w, z);
    }
    *(float4*)&xout[(size_t)p*ostride + c4*4] = m;
}

__global__ void init_gmax(unsigned* g){
    int i = blockIdx.x*256 + threadIdx.x;
    if (i < NBB*1024) g[i] = 0u;
}

// ---------------- Gb[b][o] = sum_c g[b,c] * W7[o,c]  (c < 1024) ------------
__global__ void gb_kernel(const unsigned* __restrict__ gmax, const float* __restrict__ W7,
                          float* __restrict__ Gb){
    int i = blockIdx.x*256 + threadIdx.x;
    int o = i & 511; int b = i >> 9;
    const unsigned* gm = gmax + b*1024;
    const float* w = W7 + (size_t)o*1216;
    float a0=0.f,a1=0.f,a2=0.f,a3=0.f;
    for (int c=0;c<1024;c+=4){
        a0 += dec_f(gm[c+0])*w[c+0];
        a1 += dec_f(gm[c+1])*w[c+1];
        a2 += dec_f(gm[c+2])*w[c+2];
        a3 += dec_f(gm[c+3])*w[c+3];
    }
    Gb[(size_t)b*512 + o] = (a0+a1)+(a2+a3);
}

// ---------------- fp16 tensor-core GEMM, 128x128 tile, double-buffered -----
// A/W converted fp32->fp16 on load; fp32 accumulate. Kd % 16 == 0.
__global__ void __launch_bounds__(256,2) gemm_tc(
        const float* __restrict__ A, int lda,
        const float* __restrict__ W, int ldw,
        const float* __restrict__ s, const float* __restrict__ bias,
        const float* __restrict__ Gb,
        float* __restrict__ C, int ldc, unsigned* gmax,
        int Kd, int Nd, float leak, int mode)
{
    __shared__ uint32_t As[2][128][12];   // 128 rows x 8 packed k (pad 4)
    __shared__ uint32_t Ws[2][128][12];
    int m0 = blockIdx.x*128, n0 = blockIdx.y*128;
    int tid = threadIdx.x, lane = tid & 31, w = tid >> 5;
    int gid = lane >> 2, tig = lane & 3;
    int wm = (w >> 2)*64, wn = (w & 3)*32;
    float4 acc[4][4];
    #pragma unroll
    for (int mt=0;mt<4;mt++)
        #pragma unroll
        for (int nt=0;nt<4;nt++) acc[mt][nt] = make_float4(0.f,0.f,0.f,0.f);

    int lr = tid >> 1, lq = (tid & 1)*8;   // 8 floats = 4 packed cols
    int lc = (tid & 1)*4;
    const float* Ap = A + (size_t)(m0+lr)*lda + lq;
    const float* Wp = W + (size_t)(n0+lr)*ldw + lq;

    int nk = Kd >> 4;
    float4 ta0 = *(const float4*)(Ap);
    float4 ta1 = *(const float4*)(Ap + 4);
    float4 tw0 = *(const float4*)(Wp);
    float4 tw1 = *(const float4*)(Wp + 4);
    {
        uint4 ua = {pack_h2(ta0.x,ta0.y), pack_h2(ta0.z,ta0.w),
                    pack_h2(ta1.x,ta1.y), pack_h2(ta1.z,ta1.w)};
        uint4 uw = {pack_h2(tw0.x,tw0.y), pack_h2(tw0.z,tw0.w),
                    pack_h2(tw1.x,tw1.y), pack_h2(tw1.z,tw1.w)};
        *(uint4*)&As[0][lr][lc] = ua;
        *(uint4*)&Ws[0][lr][lc] = uw;
    }
    __syncthreads();

    for (int c = 0; c < nk; c++){
        int cur = c & 1;
        if (c + 1 < nk){
            int k0 = (c+1) << 4;
            ta0 = *(const float4*)(Ap + k0);
            ta1 = *(const float4*)(Ap + k0 + 4);
            tw0 = *(const float4*)(Wp + k0);
            tw1 = *(const float4*)(Wp + k0 + 4);
        }
        uint32_t bf[4][2];
        #pragma unroll
        for (int nt=0;nt<4;nt++){
            int n = wn + nt*8 + gid;
            bf[nt][0] = Ws[cur][n][tig];
            bf[nt][1] = Ws[cur][n][tig+4];
        }
        #pragma unroll
        for (int mt=0;mt<4;mt++){
            uint32_t af[4];
            int r = wm + mt*16;
            af[0] = As[cur][r+gid  ][tig];
            af[1] = As[cur][r+gid+8][tig];
            af[2] = As[cur][r+gid  ][tig+4];
            af[3] = As[cur][r+gid+8][tig+4];
            #pragma unroll
            for (int nt=0;nt<4;nt++) mma_f16(acc[mt][nt], af, bf[nt]);
        }
        if (c + 1 < nk){
            int nxt = cur ^ 1;
            uint4 ua = {pack_h2(ta0.x,ta0.y), pack_h2(ta0.z,ta0.w),
                        pack_h2(ta1.x,ta1.y), pack_h2(ta1.z,ta1.w)};
            uint4 uw = {pack_h2(tw0.x,tw0.y), pack_h2(tw0.z,tw0.w),
                        pack_h2(tw1.x,tw1.y), pack_h2(tw1.z,tw1.w)};
            *(uint4*)&As[nxt][lr][lc] = ua;
            *(uint4*)&Ws[nxt][lr][lc] = uw;
            __syncthreads();
        }
    }

    int b = m0 >> 12;
    if (mode == 0){
        #pragma unroll
        for (int mt=0;mt<4;mt++){
            int r0 = m0 + wm + mt*16 + gid;
            #pragma unroll
            for (int nt=0;nt<4;nt++){
                int cg = n0 + wn + nt*8 + 2*tig;
                float gx = 0.f, gy = 0.f;
                if (Gb){ gx = Gb[(size_t)b*Nd + cg]; gy = Gb[(size_t)b*Nd + cg + 1]; }
                float sx=1.f, sy=1.f, bx=0.f, by=0.f;
                if (s){ sx=s[cg]; sy=s[cg+1]; bx=bias[cg]; by=bias[cg+1]; }
                else if (bias){ bx=bias[cg]; by=bias[cg+1]; }
                float4 a = acc[mt][nt];
                float z0 = sx*(a.x+gx)+bx; z0 = z0>0.f? z0 : leak*z0;
                float z1 = sy*(a.y+gy)+by; z1 = z1>0.f? z1 : leak*z1;
                float z2 = sx*(a.z+gx)+bx; z2 = z2>0.f? z2 : leak*z2;
                float z3 = sy*(a.w+gy)+by; z3 = z3>0.f? z3 : leak*z3;
                *(float2*)&C[(size_t)r0*ldc + cg]     = make_float2(z0,z1);
                *(float2*)&C[(size_t)(r0+8)*ldc + cg] = make_float2(z2,z3);
            }
        }
    } else {
        #pragma unroll
        for (int nt=0;nt<4;nt++){
            int cg = n0 + wn + nt*8 + 2*tig;
            float sx=s[cg], bx=bias[cg], sy=s[cg+1], by=bias[cg+1];
            float mx=-FLT_MAX, my=-FLT_MAX;
            #pragma unroll
            for (int mt=0;mt<4;mt++){
                float4 a = acc[mt][nt];
                float z;
                z = sx*a.x+bx; z = z>0.f? z : leak*z; mx = fmaxf(mx,z);
                z = sx*a.z+bx; z = z>0.f? z : leak*z; mx = fmaxf(mx,z);
                z = sy*a.y+by; z = z>0.f? z : leak*z; my = fmaxf(my,z);
                z = sy*a.w+by; z = z>0.f? z : leak*z; my = fmaxf(my,z);
            }
            #pragma unroll
            for (int off=4; off<32; off<<=1){
                mx = fmaxf(mx, __shfl_xor_sync(0xffffffffu, mx, off));
                my = fmaxf(my, __shfl_xor_sync(0xffffffffu, my, off));
            }
            if (gid == 0){
                atomicMax(&gmax[b*1024 + cg],     enc_f(mx));
                atomicMax(&gmax[b*1024 + cg + 1], enc_f(my));
            }
        }
    }
}

// ---------------- small fp32 GEMM kept for conv9 (transposed store) --------
__global__ void __launch_bounds__(256,2) gemm128(
        const float* __restrict__ A, int lda,
        const float* __restrict__ W, int ldw,
        const float* __restrict__ bias,
        float* __restrict__ C, int Kd, int Nd)
{
    __shared__ float As[8][132];
    __shared__ float Ws[8][132];
    int m0 = blockIdx.x*128, n0 = blockIdx.y*128;
    int tid = threadIdx.x;
    int hr = tid >> 1;
    int kq = (tid & 1)*4;
    const float* Ap = A + (size_t)(m0 + hr)*lda + kq;
    bool wval = (n0 + hr) < Nd;
    const float* Wp = W + (size_t)(n0 + (wval ? hr : 0))*ldw + kq;
    int tx = tid & 15, ty = tid >> 4;
    float acc[8][8];
    #pragma unroll
    for (int i=0;i<8;i++)
        #pragma unroll
        for (int j=0;j<8;j++) acc[i][j]=0.f;

    for (int k0 = 0; k0 < Kd; k0 += 8){
        float4 a4 = *(const float4*)(Ap + k0);
        float4 w4 = wval ? *(const float4*)(Wp + k0) : make_float4(0.f,0.f,0.f,0.f);
        As[kq+0][hr]=a4.x; As[kq+1][hr]=a4.y; As[kq+2][hr]=a4.z; As[kq+3][hr]=a4.w;
        Ws[kq+0][hr]=w4.x; Ws[kq+1][hr]=w4.y; Ws[kq+2][hr]=w4.z; Ws[kq+3][hr]=w4.w;
        __syncthreads();
        #pragma unroll
        for (int k=0;k<8;k++){
            float4 a0 = *(const float4*)&As[k][ty*4];
            float4 a1 = *(const float4*)&As[k][64+ty*4];
            float4 w0 = *(const float4*)&Ws[k][tx*4];
            float4 w1 = *(const float4*)&Ws[k][64+tx*4];
            float ar[8] = {a0.x,a0.y,a0.z,a0.w,a1.x,a1.y,a1.z,a1.w};
            float wr[8] = {w0.x,w0.y,w0.z,w0.w,w1.x,w1.y,w1.z,w1.w};
            #pragma unroll
            for (int i=0;i<8;i++)
                #pragma unroll
                for (int j=0;j<8;j++) acc[i][j] += ar[i]*wr[j];
        }
        __syncthreads();
    }
    #pragma unroll
    for (int i=0;i<8;i++){
        int m = m0 + (i<4 ? ty*4+i : 64 + ty*4 + (i-4));
        int bb_ = m >> 12, nn = m & (NNN-1);
        #pragma unroll
        for (int j=0;j<8;j++){
            int n = n0 + (j<4 ? tx*4+j : 64 + tx*4 + (j-4));
            if (n < Nd){
                float z = acc[i][j] + (bias ? bias[n] : 0.f);
                C[((size_t)bb_*Nd + n)*NNN + nn] = z;
            }
        }
    }
}

// ---------------------------------------------------------------------------
extern "C" void kernel_launch(void* const* d_in, const int* in_sizes, int n_in,
                              void* d_out, int out_size){
    const float* x  = (const float*)d_in[0];
    const float* W1 = (const float*)d_in[1];
    const float* s1 = (const float*)d_in[2];
    const float* b1 = (const float*)d_in[3];
    const float* W2 = (const float*)d_in[4];
    const float* s2 = (const float*)d_in[5];
    const float* b2 = (const float*)d_in[6];
    const float* W3 = (const float*)d_in[7];
    const float* s3 = (const float*)d_in[8];
    const float* b3 = (const float*)d_in[9];
    const float* W4 = (const float*)d_in[10];
    const float* s4 = (const float*)d_in[11];
    const float* b4 = (const float*)d_in[12];
    const float* W5 = (const float*)d_in[13];
    const float* s5 = (const float*)d_in[14];
    const float* b5 = (const float*)d_in[15];
    const float* W6 = (const float*)d_in[16];
    const float* s6 = (const float*)d_in[17];
    const float* b6 = (const float*)d_in[18];
    const float* W7 = (const float*)d_in[19];
    const float* s7 = (const float*)d_in[20];
    const float* b7 = (const float*)d_in[21];
    const float* W8 = (const float*)d_in[22];
    const float* s8 = (const float*)d_in[23];
    const float* b8 = (const float*)d_in[24];
    const float* W9 = (const float*)d_in[25];
    const float* b9 = (const float*)d_in[26];
    float* out = (float*)d_out;

    float *xcat,*PQ,*h7,*h8,*Wpq,*Gb; int* idx; unsigned* gmax;
    cudaGetSymbolAddress((void**)&idx,  d_idx);
    cudaGetSymbolAddress((void**)&xcat, d_xcat);
    cudaGetSymbolAddress((void**)&PQ,   d_PQ);
    cudaGetSymbolAddress((void**)&h7,   d_h7);
    cudaGetSymbolAddress((void**)&h8,   d_h8);
    cudaGetSymbolAddress((void**)&Wpq,  d_Wpq);
    cudaGetSymbolAddress((void**)&gmax, d_gmax);
    cudaGetSymbolAddress((void**)&Gb,   d_Gb);

    const float LK = 0.2f;
    const int edge_blocks = BN_/(EDGE_PPT*EDGE_ITER);

    knn_radix<<<BN_,256>>>(x, idx);

    // stage 1: P/Q from coords, fused edge conv (conv1+conv2) + max_k -> x1
    pq1_kernel<<<4096,256>>>(x, W1, PQ);
    fused_edge_tc<<<edge_blocks,256>>>(PQ, s1, b1, W2, s2, b2, idx, xcat + 0, 192);

    // stage 2: P/Q = x1 * Wpq3, fused edge conv (conv3+conv4) + max_k -> x2
    wprep_kernel<<<32,256>>>(W3, Wpq);
    gemm_tc<<<dim3(128,1),256>>>(xcat, 192, Wpq, 64, nullptr, nullptr, nullptr,
                                 PQ, 128, nullptr, 64, 128, 1.f, 0);
    fused_edge_tc<<<edge_blocks,256>>>(PQ, s3, b3, W4, s4, b4, idx, xcat + 64, 192);

    // stage 3: P/Q = x2 * Wpq5, gather + lrelu + max_k -> x3
    wprep_kernel<<<32,256>>>(W5, Wpq);
    gemm_tc<<<dim3(128,1),256>>>(xcat + 64, 192, Wpq, 64, nullptr, nullptr, nullptr,
                                 PQ, 128, nullptr, 64, 128, 1.f, 0);
    maxgather_kernel<<<1024,256>>>(PQ, s5, b5, idx, xcat + 128, 192);

    // conv6 (192 -> 1024) with fused max over N (atomic)
    init_gmax<<<16,256>>>(gmax);
    gemm_tc<<<dim3(128,8),256>>>(xcat, 192, W6, 192, s6, b6, nullptr,
                                 nullptr, 0, gmax, 192, 1024, LK, 2);

    // per-batch bias from g through W7's first 1024 input channels
    gb_kernel<<<8,256>>>(gmax, W7, Gb);

    // conv7: xcat (192) through W7[:,1024:] + Gb  -> h7 (512)
    gemm_tc<<<dim3(128,4),256>>>(xcat, 192, W7 + 1024, 1216, s7, b7, Gb,
                                 h7, 512, nullptr, 192, 512, LK, 0);
    // conv8: 512 -> 256
    gemm_tc<<<dim3(128,2),256>>>(h7, 512, W8, 512, s8, b8, nullptr,
                                 h8, 256, nullptr, 512, 256, LK, 0);
    // conv9: 256 -> 63, + bias, transposed store
    gemm128<<<dim3(128,1),256>>>(h8, 256, W9, 256, b9, out, 256, 63);
}